// round 2
// baseline (speedup 1.0000x reference)
#include <cuda_runtime.h>
#include <cstdint>
#include <math.h>

// ---------------- problem constants ----------------
#define BB 4
#define SS 2048
#define HH 768
#define NH 12
#define HD 64
#define TT (BB*SS)      // 8192 tokens
#define TH (TT*HH)      // 6291456

// ---------------- scratch (no allocs allowed) ----------------
__device__ float g_dw[TH];
__device__ float g_t0[TH];
__device__ float g_t1[TH];
__device__ float g_t2[TH];
__device__ float g_br[TH];
__device__ float g_q[TH];
__device__ float g_k[TH];
__device__ float g_v[TH];
__device__ float g_gate[TT];
__device__ double g_aux;
__device__ int    g_mask4[4];
__device__ int    g_cnt;

// ---------------- setup: decode mask (bool-vs-int32 robust), reset aux ----------------
__global__ void k_setup(const void* maskp)
{
    const unsigned char* pb = (const unsigned char*)maskp;
    unsigned char b0 = pb[0], b1 = pb[1], b2 = pb[2], b3 = pb[3];
    int m[4];
    if (b1 | b2 | b3) {
        // bytes 1..3 nonzero -> must be 1-byte bool layout
        m[0] = b0 != 0; m[1] = b1 != 0; m[2] = b2 != 0; m[3] = b3 != 0;
    } else {
        // ambiguous: check int32 interpretation (values must be 0/1)
        const int* pi = (const int*)maskp;
        int i1 = pi[1], i2 = pi[2], i3 = pi[3];
        bool ints_ok = ((unsigned)i1 <= 1u) && ((unsigned)i2 <= 1u) && ((unsigned)i3 <= 1u);
        if (ints_ok) { m[0] = pi[0] != 0; m[1] = i1; m[2] = i2; m[3] = i3; }
        else         { m[0] = b0 != 0;    m[1] = 0;  m[2] = 0;  m[3] = 0;  }
    }
    int c = 0;
    for (int i = 0; i < 4; i++) { g_mask4[i] = m[i]; c += m[i]; }
    g_cnt = c;
    g_aux = 0.0;
}

// ---------------- depthwise conv k=3, pad=1 (correlation) ----------------
__global__ __launch_bounds__(256) void k_dwconv(
    const float* __restrict__ prev, const float* __restrict__ w,
    const float* __restrict__ bias, float* __restrict__ out)
{
    int idx = blockIdx.x * 256 + threadIdx.x;       // over TH
    int t = idx / HH;
    int h = idx - t * HH;
    int s = t & (SS - 1);
    float acc = bias[h];
    const float* wp = w + h * 3;
    if (s > 0)      acc += prev[idx - HH] * wp[0];
    acc += prev[idx] * wp[1];
    if (s < SS - 1) acc += prev[idx + HH] * wp[2];
    out[idx] = acc;
}

// ---------------- generic NT GEMM: C[8192,768] = A[8192,768] * W[768,768]^T + bias ----------------
// 128x128 tile, BK=16, 256 threads, 8x8 micro-tile. act: 0=none, 1=exact GELU.
__global__ __launch_bounds__(256) void gemm_nt(
    const float* __restrict__ A, const float* __restrict__ W,
    const float* __restrict__ bias, float* __restrict__ C, int act)
{
    const int K = HH, N = HH;
    __shared__ float As[16][128];
    __shared__ float Bs[16][128];
    int tid = threadIdx.x;
    int tx = tid & 15, ty = tid >> 4;
    int bm = blockIdx.y * 128;
    int bn = blockIdx.x * 128;

    float acc[8][8];
    #pragma unroll
    for (int i = 0; i < 8; i++)
        #pragma unroll
        for (int j = 0; j < 8; j++) acc[i][j] = 0.f;

    for (int k0 = 0; k0 < K; k0 += 16) {
        float4 av[2], bv[2];
        int rr[2], cc[2];
        #pragma unroll
        for (int u = 0; u < 2; u++) {
            int f4 = tid + u * 256;           // 0..511
            int r  = f4 >> 2;                 // 0..127
            int c4 = (f4 & 3) * 4;            // 0,4,8,12
            rr[u] = r; cc[u] = c4;
            av[u] = *(const float4*)(A + (size_t)(bm + r) * K + k0 + c4);
            bv[u] = *(const float4*)(W + (size_t)(bn + r) * K + k0 + c4);
        }
        __syncthreads();
        #pragma unroll
        for (int u = 0; u < 2; u++) {
            As[cc[u] + 0][rr[u]] = av[u].x;
            As[cc[u] + 1][rr[u]] = av[u].y;
            As[cc[u] + 2][rr[u]] = av[u].z;
            As[cc[u] + 3][rr[u]] = av[u].w;
            Bs[cc[u] + 0][rr[u]] = bv[u].x;
            Bs[cc[u] + 1][rr[u]] = bv[u].y;
            Bs[cc[u] + 2][rr[u]] = bv[u].z;
            Bs[cc[u] + 3][rr[u]] = bv[u].w;
        }
        __syncthreads();
        #pragma unroll
        for (int kk = 0; kk < 16; kk++) {
            float4 ra0 = *(const float4*)&As[kk][ty * 8];
            float4 ra1 = *(const float4*)&As[kk][ty * 8 + 4];
            float4 rb0 = *(const float4*)&Bs[kk][tx * 8];
            float4 rb1 = *(const float4*)&Bs[kk][tx * 8 + 4];
            float ra[8] = {ra0.x, ra0.y, ra0.z, ra0.w, ra1.x, ra1.y, ra1.z, ra1.w};
            float rb[8] = {rb0.x, rb0.y, rb0.z, rb0.w, rb1.x, rb1.y, rb1.z, rb1.w};
            #pragma unroll
            for (int i = 0; i < 8; i++)
                #pragma unroll
                for (int j = 0; j < 8; j++)
                    acc[i][j] = fmaf(ra[i], rb[j], acc[i][j]);
        }
    }
    #pragma unroll
    for (int i = 0; i < 8; i++) {
        int row = bm + ty * 8 + i;
        #pragma unroll
        for (int j = 0; j < 8; j++) {
            int col = bn + tx * 8 + j;
            float v = acc[i][j] + bias[col];
            if (act == 1) v = 0.5f * v * (1.0f + erff(v * 0.70710678118654752f));
            C[(size_t)row * N + col] = v;
        }
    }
}

// ---------------- block reduce helper ----------------
__device__ __forceinline__ float blockReduceSum(float v, float* sbuf)
{
    __syncthreads();                 // protect sbuf reuse across calls
    int lane = threadIdx.x & 31, w = threadIdx.x >> 5;
    #pragma unroll
    for (int o = 16; o; o >>= 1) v += __shfl_xor_sync(0xffffffffu, v, o);
    if (lane == 0) sbuf[w] = v;
    __syncthreads();
    if (w == 0) {
        v = (lane < 8) ? sbuf[lane] : 0.f;
        #pragma unroll
        for (int o = 4; o; o >>= 1) v += __shfl_xor_sync(0xffffffffu, v, o);
        if (lane == 0) sbuf[0] = v;
    }
    __syncthreads();
    return sbuf[0];
}

// ---------------- LayerNorm over H=768: one block (256 thr) per token ----------------
__global__ __launch_bounds__(256) void ln_kernel(
    const float* __restrict__ in, const float* __restrict__ g,
    const float* __restrict__ bta, float* __restrict__ outp)
{
    __shared__ float sbuf[8];
    int row = blockIdx.x, tid = threadIdx.x;
    const float* rp = in + (size_t)row * HH;
    float v0 = rp[tid], v1 = rp[tid + 256], v2 = rp[tid + 512];
    float sum = blockReduceSum(v0 + v1 + v2, sbuf);
    float mean = sum * (1.0f / 768.0f);
    float d0 = v0 - mean, d1 = v1 - mean, d2 = v2 - mean;
    float sq = blockReduceSum(d0 * d0 + d1 * d1 + d2 * d2, sbuf);
    float scale = rsqrtf(sq * (1.0f / 768.0f) + 1e-5f);
    float* op = outp + (size_t)row * HH;
    op[tid]       = d0 * scale * g[tid]       + bta[tid];
    op[tid + 256] = d1 * scale * g[tid + 256] + bta[tid + 256];
    op[tid + 512] = d2 * scale * g[tid + 512] + bta[tid + 512];
}

// ---------------- flash attention, fp32, BQ=64, BK=64, HD=64 ----------------
// grid (S/64, NH, B), 256 threads, dynamic smem 66304 B
__global__ __launch_bounds__(256) void attn_kernel(
    const float* __restrict__ Qg, const float* __restrict__ Kg,
    const float* __restrict__ Vg, float* __restrict__ Og)
{
    extern __shared__ float sm[];
    float* Qs = sm;              // [64][65]
    float* Ks = Qs + 64 * 65;    // [64][65]
    float* Vs = Ks + 64 * 65;    // [64][64]
    float* Ps = Vs + 64 * 64;    // [64][65]

    int tid = threadIdx.x, tx = tid & 15, ty = tid >> 4;
    int qt = blockIdx.x, hh = blockIdx.y, b = blockIdx.z;
    size_t base = (size_t)b * SS * HH + hh * HD;

    // load Q tile (scaled by 1/sqrt(HD))
    #pragma unroll
    for (int u = 0; u < 4; u++) {
        int f4 = tid + u * 256;              // 0..1023
        int r = f4 >> 4;
        int c = (f4 & 15) * 4;
        float4 qv = *(const float4*)(Qg + base + (size_t)(qt * 64 + r) * HH + c);
        Qs[r * 65 + c + 0] = qv.x * 0.125f;
        Qs[r * 65 + c + 1] = qv.y * 0.125f;
        Qs[r * 65 + c + 2] = qv.z * 0.125f;
        Qs[r * 65 + c + 3] = qv.w * 0.125f;
    }

    const float NEG_INF = __int_as_float(0xff800000u);
    float m_i[4], l_i[4], oacc[4][4];
    #pragma unroll
    for (int i = 0; i < 4; i++) {
        m_i[i] = NEG_INF; l_i[i] = 0.f;
        #pragma unroll
        for (int j = 0; j < 4; j++) oacc[i][j] = 0.f;
    }

    for (int kt = 0; kt < SS / 64; kt++) {
        __syncthreads();
        #pragma unroll
        for (int u = 0; u < 4; u++) {
            int f4 = tid + u * 256;
            int r = f4 >> 4;
            int c = (f4 & 15) * 4;
            size_t gofs = base + (size_t)(kt * 64 + r) * HH + c;
            float4 kv = *(const float4*)(Kg + gofs);
            Ks[r * 65 + c + 0] = kv.x;
            Ks[r * 65 + c + 1] = kv.y;
            Ks[r * 65 + c + 2] = kv.z;
            Ks[r * 65 + c + 3] = kv.w;
            float4 vv = *(const float4*)(Vg + gofs);
            *(float4*)&Vs[r * 64 + c] = vv;
        }
        __syncthreads();

        // scores 64x64: thread has rows ty*4+i, cols tx*4+j
        float s[4][4];
        #pragma unroll
        for (int i = 0; i < 4; i++)
            #pragma unroll
            for (int j = 0; j < 4; j++) s[i][j] = 0.f;
        #pragma unroll 4
        for (int d = 0; d < 64; d++) {
            float rq[4], rk[4];
            #pragma unroll
            for (int i = 0; i < 4; i++) rq[i] = Qs[(ty * 4 + i) * 65 + d];
            #pragma unroll
            for (int j = 0; j < 4; j++) rk[j] = Ks[(tx * 4 + j) * 65 + d];
            #pragma unroll
            for (int i = 0; i < 4; i++)
                #pragma unroll
                for (int j = 0; j < 4; j++)
                    s[i][j] = fmaf(rq[i], rk[j], s[i][j]);
        }

        // online softmax per row (rows split across 16 tx lanes)
        #pragma unroll
        for (int i = 0; i < 4; i++) {
            float mx = s[i][0];
            mx = fmaxf(mx, s[i][1]); mx = fmaxf(mx, s[i][2]); mx = fmaxf(mx, s[i][3]);
            #pragma unroll
            for (int o = 8; o; o >>= 1) mx = fmaxf(mx, __shfl_xor_sync(0xffffffffu, mx, o));
            float mn = fmaxf(m_i[i], mx);
            float corr = __expf(m_i[i] - mn);
            m_i[i] = mn;
            float rs = 0.f;
            #pragma unroll
            for (int j = 0; j < 4; j++) {
                s[i][j] = __expf(s[i][j] - mn);
                rs += s[i][j];
            }
            #pragma unroll
            for (int o = 8; o; o >>= 1) rs += __shfl_xor_sync(0xffffffffu, rs, o);
            l_i[i] = l_i[i] * corr + rs;
            #pragma unroll
            for (int j = 0; j < 4; j++) {
                oacc[i][j] *= corr;
                Ps[(ty * 4 + i) * 65 + tx * 4 + j] = s[i][j];
            }
        }
        __syncthreads();

        // O += P * V
        #pragma unroll 4
        for (int n = 0; n < 64; n++) {
            float rp[4];
            #pragma unroll
            for (int i = 0; i < 4; i++) rp[i] = Ps[(ty * 4 + i) * 65 + n];
            float4 rv = *(const float4*)&Vs[n * 64 + tx * 4];
            #pragma unroll
            for (int i = 0; i < 4; i++) {
                oacc[i][0] = fmaf(rp[i], rv.x, oacc[i][0]);
                oacc[i][1] = fmaf(rp[i], rv.y, oacc[i][1]);
                oacc[i][2] = fmaf(rp[i], rv.z, oacc[i][2]);
                oacc[i][3] = fmaf(rp[i], rv.w, oacc[i][3]);
            }
        }
    }

    #pragma unroll
    for (int i = 0; i < 4; i++) {
        float inv = 1.0f / l_i[i];
        int r = qt * 64 + ty * 4 + i;
        float* op = Og + base + (size_t)r * HH + tx * 4;
        op[0] = oacc[i][0] * inv;
        op[1] = oacc[i][1] * inv;
        op[2] = oacc[i][2] * inv;
        op[3] = oacc[i][3] * inv;
    }
}

// ---------------- gate: sigmoid( [x, bridged] . Wg + bg ), one warp per token ----------------
__global__ __launch_bounds__(256) void gate_kernel(
    const float* __restrict__ x, const float* __restrict__ br,
    const float* __restrict__ Wg, const float* __restrict__ bg,
    float* __restrict__ gout)
{
    int t = blockIdx.x * 8 + (threadIdx.x >> 5);
    int lane = threadIdx.x & 31;
    const float* xr = x + (size_t)t * HH;
    const float* brr = br + (size_t)t * HH;
    float z = 0.f;
    #pragma unroll 4
    for (int h = lane; h < HH; h += 32)
        z += xr[h] * Wg[h] + brr[h] * Wg[HH + h];
    #pragma unroll
    for (int o = 16; o; o >>= 1) z += __shfl_xor_sync(0xffffffffu, z, o);
    if (lane == 0) gout[t] = 1.0f / (1.0f + __expf(-(z + bg[0])));
}

// ---------------- final: out = x + mask * gate * tanh(inj); accumulate aux ----------------
__global__ __launch_bounds__(256) void final_kernel(
    const float* __restrict__ x, const float* __restrict__ inj,
    const float* __restrict__ gate, const float* __restrict__ br,
    float* __restrict__ outp)
{
    __shared__ float sbuf[8];
    int idx = blockIdx.x * 256 + threadIdx.x;
    int t = idx / HH;
    int b = t >> 11;                 // /2048
    int mb = g_mask4[b];
    float xv = x[idx];
    float o = xv, a = 0.f;
    if (mb) {
        o = xv + gate[t] * tanhf(inj[idx]);
        float d = br[idx] - xv;
        a = d * d;
    }
    outp[idx] = o;
    float s = blockReduceSum(a, sbuf);
    if (threadIdx.x == 0 && s != 0.f) atomicAdd(&g_aux, (double)s);
}

__global__ void auxfin_kernel(float* outp, int out_size)
{
    if (out_size > TH) {
        int c = g_cnt; if (c < 1) c = 1;
        outp[TH] = (float)(g_aux / ((double)c * (double)SS * (double)HH));
    }
}

// ---------------- launch ----------------
extern "C" void kernel_launch(void* const* d_in, const int* in_sizes, int n_in,
                              void* d_out, int out_size)
{
    const float* x      = (const float*)d_in[0];
    const float* prev   = (const float*)d_in[1];
    const void*  maskp  = d_in[2];
    const float* dww    = (const float*)d_in[3];
    const float* dwb    = (const float*)d_in[4];
    const float* pww    = (const float*)d_in[5];
    const float* pwb    = (const float*)d_in[6];
    const float* cng    = (const float*)d_in[7];
    const float* cnb    = (const float*)d_in[8];
    const float* Wq     = (const float*)d_in[9];
    const float* bq     = (const float*)d_in[10];
    const float* Wk     = (const float*)d_in[11];
    const float* bk     = (const float*)d_in[12];
    const float* Wv     = (const float*)d_in[13];
    const float* bv     = (const float*)d_in[14];
    const float* Wo     = (const float*)d_in[15];
    const float* bo     = (const float*)d_in[16];
    const float* png    = (const float*)d_in[17];
    const float* pnb    = (const float*)d_in[18];
    const float* Wpost  = (const float*)d_in[19];
    const float* bpost  = (const float*)d_in[20];
    const float* Wg     = (const float*)d_in[21];
    const float* bg     = (const float*)d_in[22];
    float* out = (float*)d_out;

    float *p_dw, *p_t0, *p_t1, *p_t2, *p_br, *p_q, *p_k, *p_v, *p_g;
    cudaGetSymbolAddress((void**)&p_dw, g_dw);
    cudaGetSymbolAddress((void**)&p_t0, g_t0);
    cudaGetSymbolAddress((void**)&p_t1, g_t1);
    cudaGetSymbolAddress((void**)&p_t2, g_t2);
    cudaGetSymbolAddress((void**)&p_br, g_br);
    cudaGetSymbolAddress((void**)&p_q,  g_q);
    cudaGetSymbolAddress((void**)&p_k,  g_k);
    cudaGetSymbolAddress((void**)&p_v,  g_v);
    cudaGetSymbolAddress((void**)&p_g,  g_gate);

    const int ATTN_SMEM = (64 * 65 * 3 + 64 * 64) * 4;   // 66304
    cudaFuncSetAttribute(attn_kernel, cudaFuncAttributeMaxDynamicSharedMemorySize, ATTN_SMEM);

    dim3 ggrid(HH / 128, TT / 128);  // (6, 64)

    k_setup<<<1, 1>>>(maskp);
    k_dwconv<<<TH / 256, 256>>>(prev, dww, dwb, p_dw);
    gemm_nt<<<ggrid, 256>>>(p_dw, pww, pwb, p_t0, 1);               // PW + GELU
    ln_kernel<<<TT, 256>>>(p_t0, cng, cnb, p_br);                   // bridged
    gemm_nt<<<ggrid, 256>>>(x,    Wq, bq, p_q, 0);
    gemm_nt<<<ggrid, 256>>>(p_br, Wk, bk, p_k, 0);
    gemm_nt<<<ggrid, 256>>>(p_br, Wv, bv, p_v, 0);
    attn_kernel<<<dim3(SS / 64, NH, BB), 256, ATTN_SMEM>>>(p_q, p_k, p_v, p_t0);
    gemm_nt<<<ggrid, 256>>>(p_t0, Wo, bo, p_t1, 0);
    ln_kernel<<<TT, 256>>>(p_t1, png, pnb, p_t2);
    gemm_nt<<<ggrid, 256>>>(p_t2, Wpost, bpost, p_t1, 0);           // inj
    gate_kernel<<<TT / 8, 256>>>(x, p_br, Wg, bg, p_g);
    final_kernel<<<TH / 256, 256>>>(x, p_t1, p_g, p_br, out);
    auxfin_kernel<<<1, 1>>>(out, out_size);
}

// round 4
// speedup vs baseline: 1.4366x; 1.4366x over previous
#include <cuda_runtime.h>
#include <mma.h>
#include <cstdint>
#include <math.h>

using namespace nvcuda;

// ---------------- problem constants ----------------
#define BB 4
#define SS 2048
#define HH 768
#define NH 12
#define HD 64
#define TT (BB*SS)      // 8192 tokens
#define TH (TT*HH)      // 6291456

// ---------------- scratch (no allocs allowed) ----------------
__device__ float g_dw[TH];
__device__ float g_t0[TH];
__device__ float g_t1[TH];
__device__ float g_t2[TH];
__device__ float g_br[TH];
__device__ float g_q[TH];
__device__ float g_k[TH];
__device__ float g_v[TH];
__device__ float g_gate[TT];
__device__ double g_aux;
__device__ int    g_mask4[4];
__device__ int    g_cnt;

// ---------------- setup: decode mask (bool-vs-int32 robust), reset aux ----------------
__global__ void k_setup(const void* maskp)
{
    const unsigned char* pb = (const unsigned char*)maskp;
    unsigned char b0 = pb[0], b1 = pb[1], b2 = pb[2], b3 = pb[3];
    int m[4];
    if (b1 | b2 | b3) {
        m[0] = b0 != 0; m[1] = b1 != 0; m[2] = b2 != 0; m[3] = b3 != 0;
    } else {
        const int* pi = (const int*)maskp;
        int i1 = pi[1], i2 = pi[2], i3 = pi[3];
        bool ints_ok = ((unsigned)i1 <= 1u) && ((unsigned)i2 <= 1u) && ((unsigned)i3 <= 1u);
        if (ints_ok) { m[0] = pi[0] != 0; m[1] = i1; m[2] = i2; m[3] = i3; }
        else         { m[0] = b0 != 0;    m[1] = 0;  m[2] = 0;  m[3] = 0;  }
    }
    int c = 0;
    for (int i = 0; i < 4; i++) { g_mask4[i] = m[i]; c += m[i]; }
    g_cnt = c;
    g_aux = 0.0;
}

// ---------------- depthwise conv k=3, pad=1 ----------------
__global__ __launch_bounds__(256) void k_dwconv(
    const float* __restrict__ prev, const float* __restrict__ w,
    const float* __restrict__ bias, float* __restrict__ out)
{
    int idx = blockIdx.x * 256 + threadIdx.x;
    int t = idx / HH;
    int h = idx - t * HH;
    int s = t & (SS - 1);
    float acc = bias[h];
    const float* wp = w + h * 3;
    if (s > 0)      acc += prev[idx - HH] * wp[0];
    acc += prev[idx] * wp[1];
    if (s < SS - 1) acc += prev[idx + HH] * wp[2];
    out[idx] = acc;
}

// ---------------- TF32 tensor-core NT GEMM ----------------
// C[8192,768] = A[8192,768] * W[768,768]^T + bias.  act: 0 none, 1 exact GELU.
// 128x128 block tile, BK=16, 8 warps, each warp 64x32 (4x2 m16n16k8 frags).
#define GLDA 20   // smem leading dim (mult of 4, breaks bank stride)
__global__ __launch_bounds__(256) void gemm_tc(
    const float* __restrict__ A, const float* __restrict__ W,
    const float* __restrict__ bias, float* __restrict__ C, int act)
{
    const int K = HH;
    __shared__ float As[128 * GLDA];
    __shared__ float Ws[128 * GLDA];
    __shared__ float Eb[8][256];

    int tid = threadIdx.x;
    int wid = tid >> 5;
    int lane = tid & 31;
    int wm = wid >> 2;        // 0..1 (64 rows each)
    int wn = wid & 3;         // 0..3 (32 cols each)
    int bm = blockIdx.y * 128, bn = blockIdx.x * 128;

    wmma::fragment<wmma::accumulator, 16, 16, 8, float> acc[4][2];
    #pragma unroll
    for (int i = 0; i < 4; i++)
        #pragma unroll
        for (int j = 0; j < 2; j++) wmma::fill_fragment(acc[i][j], 0.0f);

    for (int k0 = 0; k0 < K; k0 += 16) {
        float4 av[2], bv[2];
        int rr[2], cc[2];
        #pragma unroll
        for (int u = 0; u < 2; u++) {
            int f4 = tid + u * 256;           // 0..511
            int r  = f4 >> 2;                 // 0..127
            int c4 = (f4 & 3) * 4;            // 0,4,8,12
            rr[u] = r; cc[u] = c4;
            av[u] = *(const float4*)(A + (size_t)(bm + r) * K + k0 + c4);
            bv[u] = *(const float4*)(W + (size_t)(bn + r) * K + k0 + c4);
        }
        __syncthreads();
        #pragma unroll
        for (int u = 0; u < 2; u++) {
            *(float4*)&As[rr[u] * GLDA + cc[u]] = av[u];
            *(float4*)&Ws[rr[u] * GLDA + cc[u]] = bv[u];
        }
        __syncthreads();
        #pragma unroll
        for (int ks = 0; ks < 16; ks += 8) {
            wmma::fragment<wmma::matrix_a, 16, 16, 8, wmma::precision::tf32, wmma::row_major> af[4];
            wmma::fragment<wmma::matrix_b, 16, 16, 8, wmma::precision::tf32, wmma::col_major> bf[2];
            #pragma unroll
            for (int ni = 0; ni < 2; ni++) {
                wmma::load_matrix_sync(bf[ni], &Ws[(wn * 32 + ni * 16) * GLDA + ks], GLDA);
                #pragma unroll
                for (int t = 0; t < bf[ni].num_elements; t++)
                    bf[ni].x[t] = wmma::__float_to_tf32(bf[ni].x[t]);
            }
            #pragma unroll
            for (int mi = 0; mi < 4; mi++) {
                wmma::load_matrix_sync(af[mi], &As[(wm * 64 + mi * 16) * GLDA + ks], GLDA);
                #pragma unroll
                for (int t = 0; t < af[mi].num_elements; t++)
                    af[mi].x[t] = wmma::__float_to_tf32(af[mi].x[t]);
                #pragma unroll
                for (int ni = 0; ni < 2; ni++)
                    wmma::mma_sync(acc[mi][ni], af[mi], bf[ni], acc[mi][ni]);
            }
        }
    }

    // epilogue: per-warp staging, add bias, optional GELU
    #pragma unroll
    for (int mi = 0; mi < 4; mi++) {
        #pragma unroll
        for (int ni = 0; ni < 2; ni++) {
            wmma::store_matrix_sync(&Eb[wid][0], acc[mi][ni], 16, wmma::mem_row_major);
            __syncwarp();
            int row0 = bm + wm * 64 + mi * 16;
            int col0 = bn + wn * 32 + ni * 16;
            #pragma unroll
            for (int e = lane; e < 256; e += 32) {
                int r = e >> 4, c = e & 15;
                float v = Eb[wid][e] + bias[col0 + c];
                if (act == 1) v = 0.5f * v * (1.0f + erff(v * 0.70710678118654752f));
                C[(size_t)(row0 + r) * HH + col0 + c] = v;
            }
            __syncwarp();
        }
    }
}

// ---------------- block reduce helper ----------------
__device__ __forceinline__ float blockReduceSum(float v, float* sbuf)
{
    __syncthreads();
    int lane = threadIdx.x & 31, w = threadIdx.x >> 5;
    #pragma unroll
    for (int o = 16; o; o >>= 1) v += __shfl_xor_sync(0xffffffffu, v, o);
    if (lane == 0) sbuf[w] = v;
    __syncthreads();
    if (w == 0) {
        v = (lane < 8) ? sbuf[lane] : 0.f;
        #pragma unroll
        for (int o = 4; o; o >>= 1) v += __shfl_xor_sync(0xffffffffu, v, o);
        if (lane == 0) sbuf[0] = v;
    }
    __syncthreads();
    return sbuf[0];
}

// ---------------- LayerNorm over H=768 ----------------
__global__ __launch_bounds__(256) void ln_kernel(
    const float* __restrict__ in, const float* __restrict__ g,
    const float* __restrict__ bta, float* __restrict__ outp)
{
    __shared__ float sbuf[8];
    int row = blockIdx.x, tid = threadIdx.x;
    const float* rp = in + (size_t)row * HH;
    float v0 = rp[tid], v1 = rp[tid + 256], v2 = rp[tid + 512];
    float sum = blockReduceSum(v0 + v1 + v2, sbuf);
    float mean = sum * (1.0f / 768.0f);
    float d0 = v0 - mean, d1 = v1 - mean, d2 = v2 - mean;
    float sq = blockReduceSum(d0 * d0 + d1 * d1 + d2 * d2, sbuf);
    float scale = rsqrtf(sq * (1.0f / 768.0f) + 1e-5f);
    float* op = outp + (size_t)row * HH;
    op[tid]       = d0 * scale * g[tid]       + bta[tid];
    op[tid + 256] = d1 * scale * g[tid + 256] + bta[tid + 256];
    op[tid + 512] = d2 * scale * g[tid + 512] + bta[tid + 512];
}

// ---------------- flash attention, tf32 tensor cores, BQ=64, BK=64, HD=64 ----------------
// grid (S/64, NH, B), 256 threads. smem: Qs,Ks,Vs,Ps each 64x68 f32 (Os aliases Ks).
#define ALD 68
__global__ __launch_bounds__(256) void attn_tc(
    const float* __restrict__ Qg, const float* __restrict__ Kg,
    const float* __restrict__ Vg, float* __restrict__ Og)
{
    extern __shared__ float sm[];
    float* Qs = sm;
    float* Ks = sm + 64 * ALD;
    float* Vs = sm + 2 * 64 * ALD;
    float* Ps = sm + 3 * 64 * ALD;
    float* Os = Ks;   // reuse: K tile dead after QK^T

    int tid = threadIdx.x, tx = tid & 15, ty = tid >> 4;
    int wid = tid >> 5;
    int wm = wid >> 2;     // 0..1: 32 q-rows each
    int wn = wid & 3;      // 0..3: 16 cols each
    int qt = blockIdx.x, hh = blockIdx.y, b = blockIdx.z;
    size_t base = (size_t)b * SS * HH + hh * HD;

    // load Q tile (scaled by 1/sqrt(HD))
    #pragma unroll
    for (int u = 0; u < 4; u++) {
        int f4 = tid + u * 256;              // 0..1023
        int r = f4 >> 4;
        int c = (f4 & 15) * 4;
        float4 qv = *(const float4*)(Qg + base + (size_t)(qt * 64 + r) * HH + c);
        Qs[r * ALD + c + 0] = qv.x * 0.125f;
        Qs[r * ALD + c + 1] = qv.y * 0.125f;
        Qs[r * ALD + c + 2] = qv.z * 0.125f;
        Qs[r * ALD + c + 3] = qv.w * 0.125f;
    }

    const float NEG_INF = __int_as_float(0xff800000u);
    float m_i[4], l_i[4], oacc[4][4];
    #pragma unroll
    for (int i = 0; i < 4; i++) {
        m_i[i] = NEG_INF; l_i[i] = 0.f;
        #pragma unroll
        for (int j = 0; j < 4; j++) oacc[i][j] = 0.f;
    }

    for (int kt = 0; kt < SS / 64; kt++) {
        __syncthreads();   // Os(=Ks)/Vs reads from prev iter done
        #pragma unroll
        for (int u = 0; u < 4; u++) {
            int f4 = tid + u * 256;
            int r = f4 >> 4;
            int c = (f4 & 15) * 4;
            size_t gofs = base + (size_t)(kt * 64 + r) * HH + c;
            *(float4*)&Ks[r * ALD + c] = *(const float4*)(Kg + gofs);
            *(float4*)&Vs[r * ALD + c] = *(const float4*)(Vg + gofs);
        }
        __syncthreads();

        // ---- scores = Q * K^T via tf32 mma ----
        {
            wmma::fragment<wmma::accumulator, 16, 16, 8, float> sc[2];
            wmma::fill_fragment(sc[0], 0.f);
            wmma::fill_fragment(sc[1], 0.f);
            #pragma unroll
            for (int ks = 0; ks < 64; ks += 8) {
                wmma::fragment<wmma::matrix_b, 16, 16, 8, wmma::precision::tf32, wmma::col_major> kb;
                wmma::load_matrix_sync(kb, &Ks[(wn * 16) * ALD + ks], ALD);
                #pragma unroll
                for (int t = 0; t < kb.num_elements; t++) kb.x[t] = wmma::__float_to_tf32(kb.x[t]);
                #pragma unroll
                for (int mi = 0; mi < 2; mi++) {
                    wmma::fragment<wmma::matrix_a, 16, 16, 8, wmma::precision::tf32, wmma::row_major> qa;
                    wmma::load_matrix_sync(qa, &Qs[(wm * 32 + mi * 16) * ALD + ks], ALD);
                    #pragma unroll
                    for (int t = 0; t < qa.num_elements; t++) qa.x[t] = wmma::__float_to_tf32(qa.x[t]);
                    wmma::mma_sync(sc[mi], qa, kb, sc[mi]);
                }
            }
            #pragma unroll
            for (int mi = 0; mi < 2; mi++)
                wmma::store_matrix_sync(&Ps[(wm * 32 + mi * 16) * ALD + wn * 16], sc[mi], ALD,
                                        wmma::mem_row_major);
        }
        __syncthreads();

        // ---- SIMT online softmax on Ps; scale oacc by corr ----
        #pragma unroll
        for (int i = 0; i < 4; i++) {
            int row = ty * 4 + i;
            float s0 = Ps[row * ALD + tx * 4 + 0];
            float s1 = Ps[row * ALD + tx * 4 + 1];
            float s2 = Ps[row * ALD + tx * 4 + 2];
            float s3 = Ps[row * ALD + tx * 4 + 3];
            float mx = fmaxf(fmaxf(s0, s1), fmaxf(s2, s3));
            #pragma unroll
            for (int o = 8; o; o >>= 1) mx = fmaxf(mx, __shfl_xor_sync(0xffffffffu, mx, o));
            float mn = fmaxf(m_i[i], mx);
            float corr = __expf(m_i[i] - mn);
            m_i[i] = mn;
            s0 = __expf(s0 - mn); s1 = __expf(s1 - mn);
            s2 = __expf(s2 - mn); s3 = __expf(s3 - mn);
            float rs = s0 + s1 + s2 + s3;
            #pragma unroll
            for (int o = 8; o; o >>= 1) rs += __shfl_xor_sync(0xffffffffu, rs, o);
            l_i[i] = l_i[i] * corr + rs;
            Ps[row * ALD + tx * 4 + 0] = s0;
            Ps[row * ALD + tx * 4 + 1] = s1;
            Ps[row * ALD + tx * 4 + 2] = s2;
            Ps[row * ALD + tx * 4 + 3] = s3;
            #pragma unroll
            for (int j = 0; j < 4; j++) oacc[i][j] *= corr;
        }
        __syncthreads();

        // ---- O_tile = P * V via tf32 mma ----
        {
            wmma::fragment<wmma::accumulator, 16, 16, 8, float> ov[2];
            wmma::fill_fragment(ov[0], 0.f);
            wmma::fill_fragment(ov[1], 0.f);
            #pragma unroll
            for (int ks = 0; ks < 64; ks += 8) {
                wmma::fragment<wmma::matrix_b, 16, 16, 8, wmma::precision::tf32, wmma::row_major> vb;
                wmma::load_matrix_sync(vb, &Vs[ks * ALD + wn * 16], ALD);
                #pragma unroll
                for (int t = 0; t < vb.num_elements; t++) vb.x[t] = wmma::__float_to_tf32(vb.x[t]);
                #pragma unroll
                for (int mi = 0; mi < 2; mi++) {
                    wmma::fragment<wmma::matrix_a, 16, 16, 8, wmma::precision::tf32, wmma::row_major> pa;
                    wmma::load_matrix_sync(pa, &Ps[(wm * 32 + mi * 16) * ALD + ks], ALD);
                    #pragma unroll
                    for (int t = 0; t < pa.num_elements; t++) pa.x[t] = wmma::__float_to_tf32(pa.x[t]);
                    wmma::mma_sync(ov[mi], pa, vb, ov[mi]);
                }
            }
            #pragma unroll
            for (int mi = 0; mi < 2; mi++)
                wmma::store_matrix_sync(&Os[(wm * 32 + mi * 16) * ALD + wn * 16], ov[mi], ALD,
                                        wmma::mem_row_major);
        }
        __syncthreads();

        // ---- accumulate into SIMT O registers ----
        #pragma unroll
        for (int i = 0; i < 4; i++) {
            int row = ty * 4 + i;
            #pragma unroll
            for (int j = 0; j < 4; j++)
                oacc[i][j] += Os[row * ALD + tx * 4 + j];
        }
    }

    #pragma unroll
    for (int i = 0; i < 4; i++) {
        float inv = 1.0f / l_i[i];
        int r = qt * 64 + ty * 4 + i;
        float* op = Og + base + (size_t)r * HH + tx * 4;
        op[0] = oacc[i][0] * inv;
        op[1] = oacc[i][1] * inv;
        op[2] = oacc[i][2] * inv;
        op[3] = oacc[i][3] * inv;
    }
}

// ---------------- gate: sigmoid( [x, bridged] . Wg + bg ) ----------------
__global__ __launch_bounds__(256) void gate_kernel(
    const float* __restrict__ x, const float* __restrict__ br,
    const float* __restrict__ Wg, const float* __restrict__ bg,
    float* __restrict__ gout)
{
    int t = blockIdx.x * 8 + (threadIdx.x >> 5);
    int lane = threadIdx.x & 31;
    const float* xr = x + (size_t)t * HH;
    const float* brr = br + (size_t)t * HH;
    float z = 0.f;
    #pragma unroll 4
    for (int h = lane; h < HH; h += 32)
        z += xr[h] * Wg[h] + brr[h] * Wg[HH + h];
    #pragma unroll
    for (int o = 16; o; o >>= 1) z += __shfl_xor_sync(0xffffffffu, z, o);
    if (lane == 0) gout[t] = 1.0f / (1.0f + __expf(-(z + bg[0])));
}

// ---------------- final: out = x + mask * gate * tanh(inj); accumulate aux ----------------
__global__ __launch_bounds__(256) void final_kernel(
    const float* __restrict__ x, const float* __restrict__ inj,
    const float* __restrict__ gate, const float* __restrict__ br,
    float* __restrict__ outp)
{
    __shared__ float sbuf[8];
    int idx = blockIdx.x * 256 + threadIdx.x;
    int t = idx / HH;
    int b = t >> 11;
    int mb = g_mask4[b];
    float xv = x[idx];
    float o = xv, a = 0.f;
    if (mb) {
        o = xv + gate[t] * tanhf(inj[idx]);
        float d = br[idx] - xv;
        a = d * d;
    }
    outp[idx] = o;
    float s = blockReduceSum(a, sbuf);
    if (threadIdx.x == 0 && s != 0.f) atomicAdd(&g_aux, (double)s);
}

__global__ void auxfin_kernel(float* outp, int out_size)
{
    if (out_size > TH) {
        int c = g_cnt; if (c < 1) c = 1;
        outp[TH] = (float)(g_aux / ((double)c * (double)SS * (double)HH));
    }
}

// ---------------- launch ----------------
extern "C" void kernel_launch(void* const* d_in, const int* in_sizes, int n_in,
                              void* d_out, int out_size)
{
    const float* x      = (const float*)d_in[0];
    const float* prev   = (const float*)d_in[1];
    const void*  maskp  = d_in[2];
    const float* dww    = (const float*)d_in[3];
    const float* dwb    = (const float*)d_in[4];
    const float* pww    = (const float*)d_in[5];
    const float* pwb    = (const float*)d_in[6];
    const float* cng    = (const float*)d_in[7];
    const float* cnb    = (const float*)d_in[8];
    const float* Wq     = (const float*)d_in[9];
    const float* bq     = (const float*)d_in[10];
    const float* Wk     = (const float*)d_in[11];
    const float* bk     = (const float*)d_in[12];
    const float* Wv     = (const float*)d_in[13];
    const float* bv     = (const float*)d_in[14];
    const float* Wo     = (const float*)d_in[15];
    const float* bo     = (const float*)d_in[16];
    const float* png    = (const float*)d_in[17];
    const float* pnb    = (const float*)d_in[18];
    const float* Wpost  = (const float*)d_in[19];
    const float* bpost  = (const float*)d_in[20];
    const float* Wg     = (const float*)d_in[21];
    const float* bg     = (const float*)d_in[22];
    float* out = (float*)d_out;

    float *p_dw, *p_t0, *p_t1, *p_t2, *p_br, *p_q, *p_k, *p_v, *p_g;
    cudaGetSymbolAddress((void**)&p_dw, g_dw);
    cudaGetSymbolAddress((void**)&p_t0, g_t0);
    cudaGetSymbolAddress((void**)&p_t1, g_t1);
    cudaGetSymbolAddress((void**)&p_t2, g_t2);
    cudaGetSymbolAddress((void**)&p_br, g_br);
    cudaGetSymbolAddress((void**)&p_q,  g_q);
    cudaGetSymbolAddress((void**)&p_k,  g_k);
    cudaGetSymbolAddress((void**)&p_v,  g_v);
    cudaGetSymbolAddress((void**)&p_g,  g_gate);

    const int ATTN_SMEM = 4 * 64 * ALD * 4;   // 69632 B
    cudaFuncSetAttribute(attn_tc, cudaFuncAttributeMaxDynamicSharedMemorySize, ATTN_SMEM);

    dim3 ggrid(HH / 128, TT / 128);  // (6, 64)

    k_setup<<<1, 1>>>(maskp);
    k_dwconv<<<TH / 256, 256>>>(prev, dww, dwb, p_dw);
    gemm_tc<<<ggrid, 256>>>(p_dw, pww, pwb, p_t0, 1);               // PW + GELU
    ln_kernel<<<TT, 256>>>(p_t0, cng, cnb, p_br);                   // bridged
    gemm_tc<<<ggrid, 256>>>(x,    Wq, bq, p_q, 0);
    gemm_tc<<<ggrid, 256>>>(p_br, Wk, bk, p_k, 0);
    gemm_tc<<<ggrid, 256>>>(p_br, Wv, bv, p_v, 0);
    attn_tc<<<dim3(SS / 64, NH, BB), 256, ATTN_SMEM>>>(p_q, p_k, p_v, p_t0);
    gemm_tc<<<ggrid, 256>>>(p_t0, Wo, bo, p_t1, 0);
    ln_kernel<<<TT, 256>>>(p_t1, png, pnb, p_t2);
    gemm_tc<<<ggrid, 256>>>(p_t2, Wpost, bpost, p_t1, 0);           // inj
    gate_kernel<<<TT / 8, 256>>>(x, p_br, Wg, bg, p_g);
    final_kernel<<<TH / 256, 256>>>(x, p_t1, p_g, p_br, out);
    auxfin_kernel<<<1, 1>>>(out, out_size);
}

// round 5
// speedup vs baseline: 1.6062x; 1.1181x over previous
#include <cuda_runtime.h>
#include <mma.h>
#include <cstdint>
#include <math.h>

using namespace nvcuda;

// ---------------- problem constants ----------------
#define BB 4
#define SS 2048
#define HH 768
#define NH 12
#define HD 64
#define TT (BB*SS)      // 8192 tokens
#define TH (TT*HH)      // 6291456

// ---------------- scratch (no allocs allowed) ----------------
__device__ float g_dw[TH];
__device__ float g_t0[TH];
__device__ float g_t1[TH];
__device__ float g_t2[TH];
__device__ float g_br[TH];
__device__ float g_q[TH];
__device__ float g_k[TH];
__device__ float g_v[TH];
__device__ float g_gate[TT];
__device__ double g_aux;
__device__ int    g_mask4[4];
__device__ int    g_cnt;

__device__ __forceinline__ float4 tf4(float4 v)
{
    v.x = wmma::__float_to_tf32(v.x);
    v.y = wmma::__float_to_tf32(v.y);
    v.z = wmma::__float_to_tf32(v.z);
    v.w = wmma::__float_to_tf32(v.w);
    return v;
}

// ---------------- setup: decode mask (bool-vs-int32 robust), reset aux ----------------
__global__ void k_setup(const void* maskp)
{
    const unsigned char* pb = (const unsigned char*)maskp;
    unsigned char b0 = pb[0], b1 = pb[1], b2 = pb[2], b3 = pb[3];
    int m[4];
    if (b1 | b2 | b3) {
        m[0] = b0 != 0; m[1] = b1 != 0; m[2] = b2 != 0; m[3] = b3 != 0;
    } else {
        const int* pi = (const int*)maskp;
        int i1 = pi[1], i2 = pi[2], i3 = pi[3];
        bool ints_ok = ((unsigned)i1 <= 1u) && ((unsigned)i2 <= 1u) && ((unsigned)i3 <= 1u);
        if (ints_ok) { m[0] = pi[0] != 0; m[1] = i1; m[2] = i2; m[3] = i3; }
        else         { m[0] = b0 != 0;    m[1] = 0;  m[2] = 0;  m[3] = 0;  }
    }
    int c = 0;
    for (int i = 0; i < 4; i++) { g_mask4[i] = m[i]; c += m[i]; }
    g_cnt = c;
    g_aux = 0.0;
}

// ---------------- depthwise conv k=3, pad=1 ----------------
__global__ __launch_bounds__(256) void k_dwconv(
    const float* __restrict__ prev, const float* __restrict__ w,
    const float* __restrict__ bias, float* __restrict__ out)
{
    int idx = blockIdx.x * 256 + threadIdx.x;
    int t = idx / HH;
    int h = idx - t * HH;
    int s = t & (SS - 1);
    float acc = bias[h];
    const float* wp = w + h * 3;
    if (s > 0)      acc += prev[idx - HH] * wp[0];
    acc += prev[idx] * wp[1];
    if (s < SS - 1) acc += prev[idx + HH] * wp[2];
    out[idx] = acc;
}

// ---------------- TF32 tensor-core NT GEMM ----------------
// C[8192,768] = A[8192,768] * W[768,768]^T + bias.  act: 0 none, 1 exact GELU.
// 128x128 block tile, BK=16, 8 warps, each warp 64x32 (4x2 m16n16k8 frags).
// tf32 conversion done ONCE at smem store; register prefetch of next k-tile.
#define GLDA 20
__global__ __launch_bounds__(256) void gemm_tc(
    const float* __restrict__ A, const float* __restrict__ W,
    const float* __restrict__ bias, float* __restrict__ C, int act)
{
    const int K = HH;
    __shared__ float As[128 * GLDA];
    __shared__ float Ws[128 * GLDA];
    __shared__ float Eb[8][256];

    int tid = threadIdx.x;
    int wid = tid >> 5;
    int lane = tid & 31;
    int wm = wid >> 2;        // 0..1 (64 rows each)
    int wn = wid & 3;         // 0..3 (32 cols each)
    int bm = blockIdx.y * 128, bn = blockIdx.x * 128;

    wmma::fragment<wmma::accumulator, 16, 16, 8, float> acc[4][2];
    #pragma unroll
    for (int i = 0; i < 4; i++)
        #pragma unroll
        for (int j = 0; j < 2; j++) wmma::fill_fragment(acc[i][j], 0.0f);

    int rr[2], cc[2];
    float4 av[2], bv[2];
    #pragma unroll
    for (int u = 0; u < 2; u++) {
        int f4 = tid + u * 256;
        rr[u] = f4 >> 2;
        cc[u] = (f4 & 3) * 4;
        av[u] = *(const float4*)(A + (size_t)(bm + rr[u]) * K + cc[u]);
        bv[u] = *(const float4*)(W + (size_t)(bn + rr[u]) * K + cc[u]);
    }

    for (int k0 = 0; k0 < K; k0 += 16) {
        __syncthreads();
        #pragma unroll
        for (int u = 0; u < 2; u++) {
            *(float4*)&As[rr[u] * GLDA + cc[u]] = tf4(av[u]);
            *(float4*)&Ws[rr[u] * GLDA + cc[u]] = tf4(bv[u]);
        }
        __syncthreads();
        if (k0 + 16 < K) {
            #pragma unroll
            for (int u = 0; u < 2; u++) {
                av[u] = *(const float4*)(A + (size_t)(bm + rr[u]) * K + k0 + 16 + cc[u]);
                bv[u] = *(const float4*)(W + (size_t)(bn + rr[u]) * K + k0 + 16 + cc[u]);
            }
        }
        #pragma unroll
        for (int ks = 0; ks < 16; ks += 8) {
            wmma::fragment<wmma::matrix_a, 16, 16, 8, wmma::precision::tf32, wmma::row_major> af;
            wmma::fragment<wmma::matrix_b, 16, 16, 8, wmma::precision::tf32, wmma::col_major> bf[2];
            #pragma unroll
            for (int ni = 0; ni < 2; ni++)
                wmma::load_matrix_sync(bf[ni], &Ws[(wn * 32 + ni * 16) * GLDA + ks], GLDA);
            #pragma unroll
            for (int mi = 0; mi < 4; mi++) {
                wmma::load_matrix_sync(af, &As[(wm * 64 + mi * 16) * GLDA + ks], GLDA);
                #pragma unroll
                for (int ni = 0; ni < 2; ni++)
                    wmma::mma_sync(acc[mi][ni], af, bf[ni], acc[mi][ni]);
            }
        }
    }

    // epilogue: per-warp staging, add bias, optional GELU
    #pragma unroll
    for (int mi = 0; mi < 4; mi++) {
        #pragma unroll
        for (int ni = 0; ni < 2; ni++) {
            wmma::store_matrix_sync(&Eb[wid][0], acc[mi][ni], 16, wmma::mem_row_major);
            __syncwarp();
            int row0 = bm + wm * 64 + mi * 16;
            int col0 = bn + wn * 32 + ni * 16;
            #pragma unroll
            for (int e = lane; e < 256; e += 32) {
                int r = e >> 4, c = e & 15;
                float v = Eb[wid][e] + bias[col0 + c];
                if (act == 1) v = 0.5f * v * (1.0f + erff(v * 0.70710678118654752f));
                C[(size_t)(row0 + r) * HH + col0 + c] = v;
            }
            __syncwarp();
        }
    }
}

// ---------------- block reduce helper ----------------
__device__ __forceinline__ float blockReduceSum(float v, float* sbuf)
{
    __syncthreads();
    int lane = threadIdx.x & 31, w = threadIdx.x >> 5;
    #pragma unroll
    for (int o = 16; o; o >>= 1) v += __shfl_xor_sync(0xffffffffu, v, o);
    if (lane == 0) sbuf[w] = v;
    __syncthreads();
    if (w == 0) {
        v = (lane < 8) ? sbuf[lane] : 0.f;
        #pragma unroll
        for (int o = 4; o; o >>= 1) v += __shfl_xor_sync(0xffffffffu, v, o);
        if (lane == 0) sbuf[0] = v;
    }
    __syncthreads();
    return sbuf[0];
}

// ---------------- LayerNorm over H=768 ----------------
__global__ __launch_bounds__(256) void ln_kernel(
    const float* __restrict__ in, const float* __restrict__ g,
    const float* __restrict__ bta, float* __restrict__ outp)
{
    __shared__ float sbuf[8];
    int row = blockIdx.x, tid = threadIdx.x;
    const float* rp = in + (size_t)row * HH;
    float v0 = rp[tid], v1 = rp[tid + 256], v2 = rp[tid + 512];
    float sum = blockReduceSum(v0 + v1 + v2, sbuf);
    float mean = sum * (1.0f / 768.0f);
    float d0 = v0 - mean, d1 = v1 - mean, d2 = v2 - mean;
    float sq = blockReduceSum(d0 * d0 + d1 * d1 + d2 * d2, sbuf);
    float scale = rsqrtf(sq * (1.0f / 768.0f) + 1e-5f);
    float* op = outp + (size_t)row * HH;
    op[tid]       = d0 * scale * g[tid]       + bta[tid];
    op[tid + 256] = d1 * scale * g[tid + 256] + bta[tid + 256];
    op[tid + 512] = d2 * scale * g[tid + 512] + bta[tid + 512];
}

// ---------------- flash attention, tf32 TC, BQ=128, BK=64, HD=64 ----------------
// grid (S/128, NH, B), 256 threads.
// smem: Qs[128][68], Ks[64][68], Vs[64][68], Ps[128][68] (Os aliases Ps) = 104448 B
#define ALD 68
__global__ __launch_bounds__(256) void attn_tc(
    const float* __restrict__ Qg, const float* __restrict__ Kg,
    const float* __restrict__ Vg, float* __restrict__ Og)
{
    extern __shared__ float sm[];
    float* Qs = sm;                       // 128*ALD
    float* Ks = sm + 128 * ALD;           // 64*ALD
    float* Vs = sm + 128 * ALD + 64 * ALD;
    float* Ps = sm + 128 * ALD + 2 * 64 * ALD;   // 128*ALD
    float* Os = Ps;   // reuse: P fully consumed by PV mma before O staging

    int tid = threadIdx.x;
    int wid = tid >> 5;
    int wqm = wid >> 1;     // 0..3: 32 q-rows each
    int wqn = wid & 1;      // 0..1: 32 cols each
    int row = tid >> 1;     // 0..127 softmax row
    int half = tid & 1;     // 32-col half
    int qt = blockIdx.x, hh = blockIdx.y, b = blockIdx.z;
    size_t base = (size_t)b * SS * HH + hh * HD;

    // load Q tile (scaled by 1/sqrt(HD)), convert to tf32
    #pragma unroll
    for (int u = 0; u < 8; u++) {
        int f4 = tid + u * 256;              // 0..2047
        int r = f4 >> 4;
        int c = (f4 & 15) * 4;
        float4 qv = *(const float4*)(Qg + base + (size_t)(qt * 128 + r) * HH + c);
        qv.x *= 0.125f; qv.y *= 0.125f; qv.z *= 0.125f; qv.w *= 0.125f;
        *(float4*)&Qs[r * ALD + c] = tf4(qv);
    }

    const float NEG_INF = __int_as_float(0xff800000u);
    float m_i = NEG_INF, l_i = 0.f;
    float oacc[32];
    #pragma unroll
    for (int j = 0; j < 32; j++) oacc[j] = 0.f;

    for (int kt = 0; kt < SS / 64; kt++) {
        __syncthreads();
        #pragma unroll
        for (int u = 0; u < 4; u++) {
            int f4 = tid + u * 256;          // 0..1023
            int r = f4 >> 4;
            int c = (f4 & 15) * 4;
            size_t gofs = base + (size_t)(kt * 64 + r) * HH + c;
            *(float4*)&Ks[r * ALD + c] = tf4(*(const float4*)(Kg + gofs));
            *(float4*)&Vs[r * ALD + c] = tf4(*(const float4*)(Vg + gofs));
        }
        __syncthreads();

        // ---- scores = Q * K^T (128x64) ----
        {
            wmma::fragment<wmma::accumulator, 16, 16, 8, float> sc[2][2];
            #pragma unroll
            for (int mi = 0; mi < 2; mi++)
                #pragma unroll
                for (int nj = 0; nj < 2; nj++) wmma::fill_fragment(sc[mi][nj], 0.f);
            #pragma unroll
            for (int ks = 0; ks < 64; ks += 8) {
                wmma::fragment<wmma::matrix_b, 16, 16, 8, wmma::precision::tf32, wmma::col_major> kb[2];
                #pragma unroll
                for (int nj = 0; nj < 2; nj++)
                    wmma::load_matrix_sync(kb[nj], &Ks[(wqn * 32 + nj * 16) * ALD + ks], ALD);
                #pragma unroll
                for (int mi = 0; mi < 2; mi++) {
                    wmma::fragment<wmma::matrix_a, 16, 16, 8, wmma::precision::tf32, wmma::row_major> qa;
                    wmma::load_matrix_sync(qa, &Qs[(wqm * 32 + mi * 16) * ALD + ks], ALD);
                    #pragma unroll
                    for (int nj = 0; nj < 2; nj++)
                        wmma::mma_sync(sc[mi][nj], qa, kb[nj], sc[mi][nj]);
                }
            }
            #pragma unroll
            for (int mi = 0; mi < 2; mi++)
                #pragma unroll
                for (int nj = 0; nj < 2; nj++)
                    wmma::store_matrix_sync(
                        &Ps[(wqm * 32 + mi * 16) * ALD + wqn * 32 + nj * 16],
                        sc[mi][nj], ALD, wmma::mem_row_major);
        }
        __syncthreads();

        // ---- SIMT online softmax: 2 threads per row, 32 cols each ----
        {
            float p[32];
            float* pr = &Ps[row * ALD + half * 32];
            #pragma unroll
            for (int u = 0; u < 8; u++) {
                float4 v = *(float4*)&pr[u * 4];
                p[u * 4 + 0] = v.x; p[u * 4 + 1] = v.y;
                p[u * 4 + 2] = v.z; p[u * 4 + 3] = v.w;
            }
            float mx = p[0];
            #pragma unroll
            for (int j = 1; j < 32; j++) mx = fmaxf(mx, p[j]);
            mx = fmaxf(mx, __shfl_xor_sync(0xffffffffu, mx, 1));
            float mn = fmaxf(m_i, mx);
            float corr = __expf(m_i - mn);
            m_i = mn;
            float rs = 0.f;
            #pragma unroll
            for (int j = 0; j < 32; j++) { p[j] = __expf(p[j] - mn); rs += p[j]; }
            rs += __shfl_xor_sync(0xffffffffu, rs, 1);
            l_i = l_i * corr + rs;
            #pragma unroll
            for (int j = 0; j < 32; j++) oacc[j] *= corr;
            #pragma unroll
            for (int u = 0; u < 8; u++) {
                float4 v = make_float4(p[u * 4], p[u * 4 + 1], p[u * 4 + 2], p[u * 4 + 3]);
                *(float4*)&pr[u * 4] = tf4(v);
            }
        }
        __syncthreads();

        // ---- O_tile = P * V (128x64) ----
        wmma::fragment<wmma::accumulator, 16, 16, 8, float> ov[2][2];
        #pragma unroll
        for (int mi = 0; mi < 2; mi++)
            #pragma unroll
            for (int nj = 0; nj < 2; nj++) wmma::fill_fragment(ov[mi][nj], 0.f);
        #pragma unroll
        for (int ks = 0; ks < 64; ks += 8) {
            wmma::fragment<wmma::matrix_b, 16, 16, 8, wmma::precision::tf32, wmma::row_major> vb[2];
            #pragma unroll
            for (int nj = 0; nj < 2; nj++)
                wmma::load_matrix_sync(vb[nj], &Vs[ks * ALD + wqn * 32 + nj * 16], ALD);
            #pragma unroll
            for (int mi = 0; mi < 2; mi++) {
                wmma::fragment<wmma::matrix_a, 16, 16, 8, wmma::precision::tf32, wmma::row_major> pa;
                wmma::load_matrix_sync(pa, &Ps[(wqm * 32 + mi * 16) * ALD + ks], ALD);
                #pragma unroll
                for (int nj = 0; nj < 2; nj++)
                    wmma::mma_sync(ov[mi][nj], pa, vb[nj], ov[mi][nj]);
            }
        }
        __syncthreads();   // all warps done reading Ps before overwriting with O
        #pragma unroll
        for (int mi = 0; mi < 2; mi++)
            #pragma unroll
            for (int nj = 0; nj < 2; nj++)
                wmma::store_matrix_sync(
                    &Os[(wqm * 32 + mi * 16) * ALD + wqn * 32 + nj * 16],
                    ov[mi][nj], ALD, wmma::mem_row_major);
        __syncthreads();

        // ---- accumulate into per-thread O registers ----
        {
            float* orow = &Os[row * ALD + half * 32];
            #pragma unroll
            for (int u = 0; u < 8; u++) {
                float4 v = *(float4*)&orow[u * 4];
                oacc[u * 4 + 0] += v.x; oacc[u * 4 + 1] += v.y;
                oacc[u * 4 + 2] += v.z; oacc[u * 4 + 3] += v.w;
            }
        }
    }

    float inv = 1.0f / l_i;
    float* op = Og + base + (size_t)(qt * 128 + row) * HH + half * 32;
    #pragma unroll
    for (int u = 0; u < 8; u++) {
        float4 v = make_float4(oacc[u * 4] * inv, oacc[u * 4 + 1] * inv,
                               oacc[u * 4 + 2] * inv, oacc[u * 4 + 3] * inv);
        *(float4*)&op[u * 4] = v;
    }
}

// ---------------- gate: sigmoid( [x, bridged] . Wg + bg ) ----------------
__global__ __launch_bounds__(256) void gate_kernel(
    const float* __restrict__ x, const float* __restrict__ br,
    const float* __restrict__ Wg, const float* __restrict__ bg,
    float* __restrict__ gout)
{
    int t = blockIdx.x * 8 + (threadIdx.x >> 5);
    int lane = threadIdx.x & 31;
    const float* xr = x + (size_t)t * HH;
    const float* brr = br + (size_t)t * HH;
    float z = 0.f;
    #pragma unroll 4
    for (int h = lane; h < HH; h += 32)
        z += xr[h] * Wg[h] + brr[h] * Wg[HH + h];
    #pragma unroll
    for (int o = 16; o; o >>= 1) z += __shfl_xor_sync(0xffffffffu, z, o);
    if (lane == 0) gout[t] = 1.0f / (1.0f + __expf(-(z + bg[0])));
}

// ---------------- final: out = x + mask * gate * tanh(inj); accumulate aux ----------------
__global__ __launch_bounds__(256) void final_kernel(
    const float* __restrict__ x, const float* __restrict__ inj,
    const float* __restrict__ gate, const float* __restrict__ br,
    float* __restrict__ outp)
{
    __shared__ float sbuf[8];
    int idx = blockIdx.x * 256 + threadIdx.x;
    int t = idx / HH;
    int b = t >> 11;
    int mb = g_mask4[b];
    float xv = x[idx];
    float o = xv, a = 0.f;
    if (mb) {
        o = xv + gate[t] * tanhf(inj[idx]);
        float d = br[idx] - xv;
        a = d * d;
    }
    outp[idx] = o;
    float s = blockReduceSum(a, sbuf);
    if (threadIdx.x == 0 && s != 0.f) atomicAdd(&g_aux, (double)s);
}

__global__ void auxfin_kernel(float* outp, int out_size)
{
    if (out_size > TH) {
        int c = g_cnt; if (c < 1) c = 1;
        outp[TH] = (float)(g_aux / ((double)c * (double)SS * (double)HH));
    }
}

// ---------------- launch ----------------
extern "C" void kernel_launch(void* const* d_in, const int* in_sizes, int n_in,
                              void* d_out, int out_size)
{
    const float* x      = (const float*)d_in[0];
    const float* prev   = (const float*)d_in[1];
    const void*  maskp  = d_in[2];
    const float* dww    = (const float*)d_in[3];
    const float* dwb    = (const float*)d_in[4];
    const float* pww    = (const float*)d_in[5];
    const float* pwb    = (const float*)d_in[6];
    const float* cng    = (const float*)d_in[7];
    const float* cnb    = (const float*)d_in[8];
    const float* Wq     = (const float*)d_in[9];
    const float* bq     = (const float*)d_in[10];
    const float* Wk     = (const float*)d_in[11];
    const float* bk     = (const float*)d_in[12];
    const float* Wv     = (const float*)d_in[13];
    const float* bv     = (const float*)d_in[14];
    const float* Wo     = (const float*)d_in[15];
    const float* bo     = (const float*)d_in[16];
    const float* png    = (const float*)d_in[17];
    const float* pnb    = (const float*)d_in[18];
    const float* Wpost  = (const float*)d_in[19];
    const float* bpost  = (const float*)d_in[20];
    const float* Wg     = (const float*)d_in[21];
    const float* bg     = (const float*)d_in[22];
    float* out = (float*)d_out;

    float *p_dw, *p_t0, *p_t1, *p_t2, *p_br, *p_q, *p_k, *p_v, *p_g;
    cudaGetSymbolAddress((void**)&p_dw, g_dw);
    cudaGetSymbolAddress((void**)&p_t0, g_t0);
    cudaGetSymbolAddress((void**)&p_t1, g_t1);
    cudaGetSymbolAddress((void**)&p_t2, g_t2);
    cudaGetSymbolAddress((void**)&p_br, g_br);
    cudaGetSymbolAddress((void**)&p_q,  g_q);
    cudaGetSymbolAddress((void**)&p_k,  g_k);
    cudaGetSymbolAddress((void**)&p_v,  g_v);
    cudaGetSymbolAddress((void**)&p_g,  g_gate);

    const int ATTN_SMEM = (128 * ALD + 64 * ALD * 2 + 128 * ALD) * 4;   // 104448 B
    cudaFuncSetAttribute(attn_tc, cudaFuncAttributeMaxDynamicSharedMemorySize, ATTN_SMEM);

    dim3 ggrid(HH / 128, TT / 128);  // (6, 64)

    k_setup<<<1, 1>>>(maskp);
    k_dwconv<<<TH / 256, 256>>>(prev, dww, dwb, p_dw);
    gemm_tc<<<ggrid, 256>>>(p_dw, pww, pwb, p_t0, 1);               // PW + GELU
    ln_kernel<<<TT, 256>>>(p_t0, cng, cnb, p_br);                   // bridged
    gemm_tc<<<ggrid, 256>>>(x,    Wq, bq, p_q, 0);
    gemm_tc<<<ggrid, 256>>>(p_br, Wk, bk, p_k, 0);
    gemm_tc<<<ggrid, 256>>>(p_br, Wv, bv, p_v, 0);
    attn_tc<<<dim3(SS / 128, NH, BB), 256, ATTN_SMEM>>>(p_q, p_k, p_v, p_t0);
    gemm_tc<<<ggrid, 256>>>(p_t0, Wo, bo, p_t1, 0);
    ln_kernel<<<TT, 256>>>(p_t1, png, pnb, p_t2);
    gemm_tc<<<ggrid, 256>>>(p_t2, Wpost, bpost, p_t1, 0);           // inj
    gate_kernel<<<TT / 8, 256>>>(x, p_br, Wg, bg, p_g);
    final_kernel<<<TH / 256, 256>>>(x, p_t1, p_g, p_br, out);
    auxfin_kernel<<<1, 1>>>(out, out_size);
}

// round 7
// speedup vs baseline: 1.7070x; 1.0628x over previous
#include <cuda_runtime.h>
#include <mma.h>
#include <cstdint>
#include <math.h>

using namespace nvcuda;

// ---------------- problem constants ----------------
#define BB 4
#define SS 2048
#define HH 768
#define NH 12
#define HD 64
#define TT (BB*SS)      // 8192 tokens
#define TH (TT*HH)      // 6291456

// ---------------- scratch (no allocs allowed) ----------------
__device__ float g_dw[TH];
__device__ float g_t0[TH];
__device__ float g_t1[TH];
__device__ float g_t2[TH];
__device__ float g_br[TH];
__device__ float g_q[TH];
__device__ float g_k[TH];
__device__ float g_v[TH];
__device__ float g_gate[TT];
__device__ double g_aux;
__device__ int    g_mask4[4];
__device__ int    g_cnt;

// ---------------- small helpers ----------------
__device__ __forceinline__ float4 tf4(float4 v)
{
    v.x = wmma::__float_to_tf32(v.x);
    v.y = wmma::__float_to_tf32(v.y);
    v.z = wmma::__float_to_tf32(v.z);
    v.w = wmma::__float_to_tf32(v.w);
    return v;
}

__device__ __forceinline__ uint32_t smem_u32(const void* p)
{
    uint32_t a;
    asm("{ .reg .u64 t; cvta.to.shared.u64 t, %1; cvt.u32.u64 %0, t; }" : "=r"(a) : "l"(p));
    return a;
}

#define CP16(dst, src) \
    asm volatile("cp.async.cg.shared.global [%0], [%1], 16;" :: "r"(dst), "l"(src))
#define CP_COMMIT() asm volatile("cp.async.commit_group;" ::: "memory")

// ---------------- setup: decode mask (bool-vs-int32 robust), reset aux ----------------
__global__ void k_setup(const void* maskp)
{
    const unsigned char* pb = (const unsigned char*)maskp;
    unsigned char b0 = pb[0], b1 = pb[1], b2 = pb[2], b3 = pb[3];
    int m[4];
    if (b1 | b2 | b3) {
        m[0] = b0 != 0; m[1] = b1 != 0; m[2] = b2 != 0; m[3] = b3 != 0;
    } else {
        const int* pi = (const int*)maskp;
        int i1 = pi[1], i2 = pi[2], i3 = pi[3];
        bool ints_ok = ((unsigned)i1 <= 1u) && ((unsigned)i2 <= 1u) && ((unsigned)i3 <= 1u);
        if (ints_ok) { m[0] = pi[0] != 0; m[1] = i1; m[2] = i2; m[3] = i3; }
        else         { m[0] = b0 != 0;    m[1] = 0;  m[2] = 0;  m[3] = 0;  }
    }
    int c = 0;
    for (int i = 0; i < 4; i++) { g_mask4[i] = m[i]; c += m[i]; }
    g_cnt = c;
    g_aux = 0.0;
}

// ---------------- depthwise conv k=3, pad=1 ----------------
__global__ __launch_bounds__(256) void k_dwconv(
    const float* __restrict__ prev, const float* __restrict__ w,
    const float* __restrict__ bias, float* __restrict__ out)
{
    int idx = blockIdx.x * 256 + threadIdx.x;
    int t = idx / HH;
    int h = idx - t * HH;
    int s = t & (SS - 1);
    float acc = bias[h];
    const float* wp = w + h * 3;
    if (s > 0)      acc += prev[idx - HH] * wp[0];
    acc += prev[idx] * wp[1];
    if (s < SS - 1) acc += prev[idx + HH] * wp[2];
    out[idx] = acc;
}

// ---------------- TF32 wmma NT GEMM, 3-stage cp.async pipeline ----------------
// C[8192,768] = A[8192,768] * W[768,768]^T + bias.  act: 0 none, 1 exact GELU.
// 128x128 CTA tile, BK=32, 8 warps (64x32 each), 3 smem stages.
#define GL 36                       // padded row stride (floats)
#define GTILE (128 * GL)            // floats per tile (A or W)
#define GSTG  (2 * GTILE)           // floats per stage (A + W)
#define GS_BYTES (3 * GSTG * 4)     // 110592 B dynamic smem

__device__ __forceinline__ void g6_load(
    const float* __restrict__ A, const float* __restrict__ W,
    uint32_t sb, int bm, int bn, int c, int slot, int tid)
{
    int k0 = c * 32;
    uint32_t abase = sb + (uint32_t)slot * (GSTG * 4);
    uint32_t wbase = abase + GTILE * 4;
    #pragma unroll
    for (int i = 0; i < 4; i++) {
        int idx = tid + i * 256;          // 0..1023
        int r = idx >> 3;                 // row 0..127
        int j = idx & 7;                  // 16B block 0..7
        uint32_t d = (uint32_t)(r * (GL * 4) + j * 16);
        CP16(abase + d, A + (size_t)(bm + r) * HH + k0 + j * 4);
        CP16(wbase + d, W + (size_t)(bn + r) * HH + k0 + j * 4);
    }
}

__global__ __launch_bounds__(256) void gemm_tc(
    const float* __restrict__ A, const float* __restrict__ W,
    const float* __restrict__ bias, float* __restrict__ C, int act)
{
    extern __shared__ __align__(16) float gsm[];
    uint32_t sb = smem_u32(gsm);
    int tid = threadIdx.x;
    int wid = tid >> 5;
    int lane = tid & 31;
    int wm = wid >> 2;        // 0..1 (64 rows each)
    int wn = wid & 3;         // 0..3 (32 cols each)
    int bm = blockIdx.y * 128, bn = blockIdx.x * 128;

    wmma::fragment<wmma::accumulator, 16, 16, 8, float> acc[4][2];
    #pragma unroll
    for (int i = 0; i < 4; i++)
        #pragma unroll
        for (int j = 0; j < 2; j++) wmma::fill_fragment(acc[i][j], 0.0f);

    // preload stages 0,1
    g6_load(A, W, sb, bm, bn, 0, 0, tid);
    CP_COMMIT();
    g6_load(A, W, sb, bm, bn, 1, 1, tid);
    CP_COMMIT();

    for (int c = 0; c < 24; c++) {
        if (c < 23) asm volatile("cp.async.wait_group 1;" ::: "memory");
        else        asm volatile("cp.async.wait_group 0;" ::: "memory");
        __syncthreads();

        int slot = c % 3;
        const float* As = gsm + slot * GSTG;
        const float* Ws = As + GTILE;

        #pragma unroll
        for (int ks = 0; ks < 32; ks += 8) {
            wmma::fragment<wmma::matrix_a, 16, 16, 8, wmma::precision::tf32, wmma::row_major> af;
            wmma::fragment<wmma::matrix_b, 16, 16, 8, wmma::precision::tf32, wmma::col_major> bf[2];
            #pragma unroll
            for (int ni = 0; ni < 2; ni++)
                wmma::load_matrix_sync(bf[ni], &Ws[(wn * 32 + ni * 16) * GL + ks], GL);
            #pragma unroll
            for (int mi = 0; mi < 4; mi++) {
                wmma::load_matrix_sync(af, &As[(wm * 64 + mi * 16) * GL + ks], GL);
                #pragma unroll
                for (int ni = 0; ni < 2; ni++)
                    wmma::mma_sync(acc[mi][ni], af, bf[ni], acc[mi][ni]);
            }
        }

        if (c + 2 < 24) {
            g6_load(A, W, sb, bm, bn, c + 2, (c + 2) % 3, tid);
            CP_COMMIT();
        }
    }

    // epilogue: reuse dynamic smem for staging
    __syncthreads();
    float* Eb = gsm + wid * 256;
    #pragma unroll
    for (int mi = 0; mi < 4; mi++) {
        #pragma unroll
        for (int ni = 0; ni < 2; ni++) {
            wmma::store_matrix_sync(Eb, acc[mi][ni], 16, wmma::mem_row_major);
            __syncwarp();
            int row0 = bm + wm * 64 + mi * 16;
            int col0 = bn + wn * 32 + ni * 16;
            #pragma unroll
            for (int e = lane; e < 256; e += 32) {
                int r = e >> 4, cc = e & 15;
                float v = Eb[e] + bias[col0 + cc];
                if (act == 1) v = 0.5f * v * (1.0f + erff(v * 0.70710678118654752f));
                C[(size_t)(row0 + r) * HH + col0 + cc] = v;
            }
            __syncwarp();
        }
    }
}

// ---------------- block reduce helper ----------------
__device__ __forceinline__ float blockReduceSum(float v, float* sbuf)
{
    __syncthreads();
    int lane = threadIdx.x & 31, w = threadIdx.x >> 5;
    #pragma unroll
    for (int o = 16; o; o >>= 1) v += __shfl_xor_sync(0xffffffffu, v, o);
    if (lane == 0) sbuf[w] = v;
    __syncthreads();
    if (w == 0) {
        v = (lane < 8) ? sbuf[lane] : 0.f;
        #pragma unroll
        for (int o = 4; o; o >>= 1) v += __shfl_xor_sync(0xffffffffu, v, o);
        if (lane == 0) sbuf[0] = v;
    }
    __syncthreads();
    return sbuf[0];
}

// ---------------- LayerNorm over H=768 ----------------
__global__ __launch_bounds__(256) void ln_kernel(
    const float* __restrict__ in, const float* __restrict__ g,
    const float* __restrict__ bta, float* __restrict__ outp)
{
    __shared__ float sbuf[8];
    int row = blockIdx.x, tid = threadIdx.x;
    const float* rp = in + (size_t)row * HH;
    float v0 = rp[tid], v1 = rp[tid + 256], v2 = rp[tid + 512];
    float sum = blockReduceSum(v0 + v1 + v2, sbuf);
    float mean = sum * (1.0f / 768.0f);
    float d0 = v0 - mean, d1 = v1 - mean, d2 = v2 - mean;
    float sq = blockReduceSum(d0 * d0 + d1 * d1 + d2 * d2, sbuf);
    float scale = rsqrtf(sq * (1.0f / 768.0f) + 1e-5f);
    float* op = outp + (size_t)row * HH;
    op[tid]       = d0 * scale * g[tid]       + bta[tid];
    op[tid + 256] = d1 * scale * g[tid + 256] + bta[tid + 256];
    op[tid + 512] = d2 * scale * g[tid + 512] + bta[tid + 512];
}

// ---------------- flash attention, tf32 wmma, BQ=128, BK=64, HD=64 ----------------
#define ALD 68
__global__ __launch_bounds__(256) void attn_tc(
    const float* __restrict__ Qg, const float* __restrict__ Kg,
    const float* __restrict__ Vg, float* __restrict__ Og)
{
    extern __shared__ float sm[];
    float* Qs = sm;                       // 128*ALD
    float* Ks = sm + 128 * ALD;           // 64*ALD
    float* Vs = sm + 128 * ALD + 64 * ALD;
    float* Ps = sm + 128 * ALD + 2 * 64 * ALD;   // 128*ALD
    float* Os = Ps;

    int tid = threadIdx.x;
    int wid = tid >> 5;
    int wqm = wid >> 1;
    int wqn = wid & 1;
    int row = tid >> 1;
    int half = tid & 1;
    int qt = blockIdx.x, hh = blockIdx.y, b = blockIdx.z;
    size_t base = (size_t)b * SS * HH + hh * HD;

    #pragma unroll
    for (int u = 0; u < 8; u++) {
        int f4 = tid + u * 256;
        int r = f4 >> 4;
        int c = (f4 & 15) * 4;
        float4 qv = *(const float4*)(Qg + base + (size_t)(qt * 128 + r) * HH + c);
        qv.x *= 0.125f; qv.y *= 0.125f; qv.z *= 0.125f; qv.w *= 0.125f;
        *(float4*)&Qs[r * ALD + c] = tf4(qv);
    }

    const float NEG_INF = __int_as_float(0xff800000u);
    float m_i = NEG_INF, l_i = 0.f;
    float oacc[32];
    #pragma unroll
    for (int j = 0; j < 32; j++) oacc[j] = 0.f;

    for (int kt = 0; kt < SS / 64; kt++) {
        __syncthreads();
        #pragma unroll
        for (int u = 0; u < 4; u++) {
            int f4 = tid + u * 256;
            int r = f4 >> 4;
            int c = (f4 & 15) * 4;
            size_t gofs = base + (size_t)(kt * 64 + r) * HH + c;
            *(float4*)&Ks[r * ALD + c] = tf4(*(const float4*)(Kg + gofs));
            *(float4*)&Vs[r * ALD + c] = tf4(*(const float4*)(Vg + gofs));
        }
        __syncthreads();

        {
            wmma::fragment<wmma::accumulator, 16, 16, 8, float> sc[2][2];
            #pragma unroll
            for (int mi = 0; mi < 2; mi++)
                #pragma unroll
                for (int nj = 0; nj < 2; nj++) wmma::fill_fragment(sc[mi][nj], 0.f);
            #pragma unroll
            for (int ks = 0; ks < 64; ks += 8) {
                wmma::fragment<wmma::matrix_b, 16, 16, 8, wmma::precision::tf32, wmma::col_major> kb[2];
                #pragma unroll
                for (int nj = 0; nj < 2; nj++)
                    wmma::load_matrix_sync(kb[nj], &Ks[(wqn * 32 + nj * 16) * ALD + ks], ALD);
                #pragma unroll
                for (int mi = 0; mi < 2; mi++) {
                    wmma::fragment<wmma::matrix_a, 16, 16, 8, wmma::precision::tf32, wmma::row_major> qa;
                    wmma::load_matrix_sync(qa, &Qs[(wqm * 32 + mi * 16) * ALD + ks], ALD);
                    #pragma unroll
                    for (int nj = 0; nj < 2; nj++)
                        wmma::mma_sync(sc[mi][nj], qa, kb[nj], sc[mi][nj]);
                }
            }
            #pragma unroll
            for (int mi = 0; mi < 2; mi++)
                #pragma unroll
                for (int nj = 0; nj < 2; nj++)
                    wmma::store_matrix_sync(
                        &Ps[(wqm * 32 + mi * 16) * ALD + wqn * 32 + nj * 16],
                        sc[mi][nj], ALD, wmma::mem_row_major);
        }
        __syncthreads();

        {
            float p[32];
            float* pr = &Ps[row * ALD + half * 32];
            #pragma unroll
            for (int u = 0; u < 8; u++) {
                float4 v = *(float4*)&pr[u * 4];
                p[u * 4 + 0] = v.x; p[u * 4 + 1] = v.y;
                p[u * 4 + 2] = v.z; p[u * 4 + 3] = v.w;
            }
            float mx = p[0];
            #pragma unroll
            for (int j = 1; j < 32; j++) mx = fmaxf(mx, p[j]);
            mx = fmaxf(mx, __shfl_xor_sync(0xffffffffu, mx, 1));
            float mn = fmaxf(m_i, mx);
            float corr = __expf(m_i - mn);
            m_i = mn;
            float rs = 0.f;
            #pragma unroll
            for (int j = 0; j < 32; j++) { p[j] = __expf(p[j] - mn); rs += p[j]; }
            rs += __shfl_xor_sync(0xffffffffu, rs, 1);
            l_i = l_i * corr + rs;
            #pragma unroll
            for (int j = 0; j < 32; j++) oacc[j] *= corr;
            #pragma unroll
            for (int u = 0; u < 8; u++) {
                float4 v = make_float4(p[u * 4], p[u * 4 + 1], p[u * 4 + 2], p[u * 4 + 3]);
                *(float4*)&pr[u * 4] = tf4(v);
            }
        }
        __syncthreads();

        wmma::fragment<wmma::accumulator, 16, 16, 8, float> ov[2][2];
        #pragma unroll
        for (int mi = 0; mi < 2; mi++)
            #pragma unroll
            for (int nj = 0; nj < 2; nj++) wmma::fill_fragment(ov[mi][nj], 0.f);
        #pragma unroll
        for (int ks = 0; ks < 64; ks += 8) {
            wmma::fragment<wmma::matrix_b, 16, 16, 8, wmma::precision::tf32, wmma::row_major> vb[2];
            #pragma unroll
            for (int nj = 0; nj < 2; nj++)
                wmma::load_matrix_sync(vb[nj], &Vs[ks * ALD + wqn * 32 + nj * 16], ALD);
            #pragma unroll
            for (int mi = 0; mi < 2; mi++) {
                wmma::fragment<wmma::matrix_a, 16, 16, 8, wmma::precision::tf32, wmma::row_major> pa;
                wmma::load_matrix_sync(pa, &Ps[(wqm * 32 + mi * 16) * ALD + ks], ALD);
                #pragma unroll
                for (int nj = 0; nj < 2; nj++)
                    wmma::mma_sync(ov[mi][nj], pa, vb[nj], ov[mi][nj]);
            }
        }
        __syncthreads();
        #pragma unroll
        for (int mi = 0; mi < 2; mi++)
            #pragma unroll
            for (int nj = 0; nj < 2; nj++)
                wmma::store_matrix_sync(
                    &Os[(wqm * 32 + mi * 16) * ALD + wqn * 32 + nj * 16],
                    ov[mi][nj], ALD, wmma::mem_row_major);
        __syncthreads();

        {
            float* orow = &Os[row * ALD + half * 32];
            #pragma unroll
            for (int u = 0; u < 8; u++) {
                float4 v = *(float4*)&orow[u * 4];
                oacc[u * 4 + 0] += v.x; oacc[u * 4 + 1] += v.y;
                oacc[u * 4 + 2] += v.z; oacc[u * 4 + 3] += v.w;
            }
        }
    }

    float inv = 1.0f / l_i;
    float* op = Og + base + (size_t)(qt * 128 + row) * HH + half * 32;
    #pragma unroll
    for (int u = 0; u < 8; u++) {
        float4 v = make_float4(oacc[u * 4] * inv, oacc[u * 4 + 1] * inv,
                               oacc[u * 4 + 2] * inv, oacc[u * 4 + 3] * inv);
        *(float4*)&op[u * 4] = v;
    }
}

// ---------------- gate: sigmoid( [x, bridged] . Wg + bg ) ----------------
__global__ __launch_bounds__(256) void gate_kernel(
    const float* __restrict__ x, const float* __restrict__ br,
    const float* __restrict__ Wg, const float* __restrict__ bg,
    float* __restrict__ gout)
{
    int t = blockIdx.x * 8 + (threadIdx.x >> 5);
    int lane = threadIdx.x & 31;
    const float* xr = x + (size_t)t * HH;
    const float* brr = br + (size_t)t * HH;
    float z = 0.f;
    #pragma unroll 4
    for (int h = lane; h < HH; h += 32)
        z += xr[h] * Wg[h] + brr[h] * Wg[HH + h];
    #pragma unroll
    for (int o = 16; o; o >>= 1) z += __shfl_xor_sync(0xffffffffu, z, o);
    if (lane == 0) gout[t] = 1.0f / (1.0f + __expf(-(z + bg[0])));
}

// ---------------- final: out = x + mask * gate * tanh(inj); accumulate aux ----------------
__global__ __launch_bounds__(256) void final_kernel(
    const float* __restrict__ x, const float* __restrict__ inj,
    const float* __restrict__ gate, const float* __restrict__ br,
    float* __restrict__ outp)
{
    __shared__ float sbuf[8];
    int idx = blockIdx.x * 256 + threadIdx.x;
    int t = idx / HH;
    int b = t >> 11;
    int mb = g_mask4[b];
    float xv = x[idx];
    float o = xv, a = 0.f;
    if (mb) {
        o = xv + gate[t] * tanhf(inj[idx]);
        float d = br[idx] - xv;
        a = d * d;
    }
    outp[idx] = o;
    float s = blockReduceSum(a, sbuf);
    if (threadIdx.x == 0 && s != 0.f) atomicAdd(&g_aux, (double)s);
}

__global__ void auxfin_kernel(float* outp, int out_size)
{
    if (out_size > TH) {
        int c = g_cnt; if (c < 1) c = 1;
        outp[TH] = (float)(g_aux / ((double)c * (double)SS * (double)HH));
    }
}

// ---------------- launch ----------------
extern "C" void kernel_launch(void* const* d_in, const int* in_sizes, int n_in,
                              void* d_out, int out_size)
{
    const float* x      = (const float*)d_in[0];
    const float* prev   = (const float*)d_in[1];
    const void*  maskp  = d_in[2];
    const float* dww    = (const float*)d_in[3];
    const float* dwb    = (const float*)d_in[4];
    const float* pww    = (const float*)d_in[5];
    const float* pwb    = (const float*)d_in[6];
    const float* cng    = (const float*)d_in[7];
    const float* cnb    = (const float*)d_in[8];
    const float* Wq     = (const float*)d_in[9];
    const float* bq     = (const float*)d_in[10];
    const float* Wk     = (const float*)d_in[11];
    const float* bk     = (const float*)d_in[12];
    const float* Wv     = (const float*)d_in[13];
    const float* bv     = (const float*)d_in[14];
    const float* Wo     = (const float*)d_in[15];
    const float* bo     = (const float*)d_in[16];
    const float* png    = (const float*)d_in[17];
    const float* pnb    = (const float*)d_in[18];
    const float* Wpost  = (const float*)d_in[19];
    const float* bpost  = (const float*)d_in[20];
    const float* Wg     = (const float*)d_in[21];
    const float* bg     = (const float*)d_in[22];
    float* out = (float*)d_out;

    float *p_dw, *p_t0, *p_t1, *p_t2, *p_br, *p_q, *p_k, *p_v, *p_g;
    cudaGetSymbolAddress((void**)&p_dw, g_dw);
    cudaGetSymbolAddress((void**)&p_t0, g_t0);
    cudaGetSymbolAddress((void**)&p_t1, g_t1);
    cudaGetSymbolAddress((void**)&p_t2, g_t2);
    cudaGetSymbolAddress((void**)&p_br, g_br);
    cudaGetSymbolAddress((void**)&p_q,  g_q);
    cudaGetSymbolAddress((void**)&p_k,  g_k);
    cudaGetSymbolAddress((void**)&p_v,  g_v);
    cudaGetSymbolAddress((void**)&p_g,  g_gate);

    const int ATTN_SMEM = (128 * ALD + 64 * ALD * 2 + 128 * ALD) * 4;   // 104448 B
    cudaFuncSetAttribute(attn_tc, cudaFuncAttributeMaxDynamicSharedMemorySize, ATTN_SMEM);
    cudaFuncSetAttribute(gemm_tc, cudaFuncAttributeMaxDynamicSharedMemorySize, GS_BYTES);

    dim3 ggrid(HH / 128, TT / 128);  // (6, 64)

    k_setup<<<1, 1>>>(maskp);
    k_dwconv<<<TH / 256, 256>>>(prev, dww, dwb, p_dw);
    gemm_tc<<<ggrid, 256, GS_BYTES>>>(p_dw, pww, pwb, p_t0, 1);     // PW + GELU
    ln_kernel<<<TT, 256>>>(p_t0, cng, cnb, p_br);                   // bridged
    gemm_tc<<<ggrid, 256, GS_BYTES>>>(x,    Wq, bq, p_q, 0);
    gemm_tc<<<ggrid, 256, GS_BYTES>>>(p_br, Wk, bk, p_k, 0);
    gemm_tc<<<ggrid, 256, GS_BYTES>>>(p_br, Wv, bv, p_v, 0);
    attn_tc<<<dim3(SS / 128, NH, BB), 256, ATTN_SMEM>>>(p_q, p_k, p_v, p_t0);
    gemm_tc<<<ggrid, 256, GS_BYTES>>>(p_t0, Wo, bo, p_t1, 0);
    ln_kernel<<<TT, 256>>>(p_t1, png, pnb, p_t2);
    gemm_tc<<<ggrid, 256, GS_BYTES>>>(p_t2, Wpost, bpost, p_t1, 0); // inj
    gate_kernel<<<TT / 8, 256>>>(x, p_br, Wg, bg, p_g);
    final_kernel<<<TH / 256, 256>>>(x, p_t1, p_g, p_br, out);
    auxfin_kernel<<<1, 1>>>(out, out_size);
}

// round 8
// speedup vs baseline: 2.5351x; 1.4851x over previous
#include <cuda_runtime.h>
#include <mma.h>
#include <cstdint>
#include <math.h>

using namespace nvcuda;

// ---------------- problem constants ----------------
#define BB 4
#define SS 2048
#define HH 768
#define NH 12
#define HD 64
#define TT (BB*SS)      // 8192 tokens
#define TH (TT*HH)      // 6291456

// ---------------- scratch (no allocs allowed) ----------------
__device__ float g_dw[TH];
__device__ float g_t0[TH];
__device__ float g_t1[TH];
__device__ float g_t2[TH];
__device__ float g_br[TH];
__device__ float g_q[TH];
__device__ float g_k[TH];
__device__ float g_v[TH];
__device__ double g_aux;
__device__ int    g_mask4[4];
__device__ int    g_cnt;

// ---------------- small helpers ----------------
__device__ __forceinline__ float4 tf4(float4 v)
{
    v.x = wmma::__float_to_tf32(v.x);
    v.y = wmma::__float_to_tf32(v.y);
    v.z = wmma::__float_to_tf32(v.z);
    v.w = wmma::__float_to_tf32(v.w);
    return v;
}

__device__ __forceinline__ uint32_t smem_u32(const void* p)
{
    uint32_t a;
    asm("{ .reg .u64 t; cvta.to.shared.u64 t, %1; cvt.u32.u64 %0, t; }" : "=r"(a) : "l"(p));
    return a;
}

#define CP16(dst, src) \
    asm volatile("cp.async.cg.shared.global [%0], [%1], 16;" :: "r"(dst), "l"(src))
#define CP_COMMIT() asm volatile("cp.async.commit_group;" ::: "memory")

// ---------------- setup: decode mask (bool-vs-int32 robust), reset aux ----------------
__global__ void k_setup(const void* maskp)
{
    const unsigned char* pb = (const unsigned char*)maskp;
    unsigned char b0 = pb[0], b1 = pb[1], b2 = pb[2], b3 = pb[3];
    int m[4];
    if (b1 | b2 | b3) {
        m[0] = b0 != 0; m[1] = b1 != 0; m[2] = b2 != 0; m[3] = b3 != 0;
    } else {
        const int* pi = (const int*)maskp;
        int i1 = pi[1], i2 = pi[2], i3 = pi[3];
        bool ints_ok = ((unsigned)i1 <= 1u) && ((unsigned)i2 <= 1u) && ((unsigned)i3 <= 1u);
        if (ints_ok) { m[0] = pi[0] != 0; m[1] = i1; m[2] = i2; m[3] = i3; }
        else         { m[0] = b0 != 0;    m[1] = 0;  m[2] = 0;  m[3] = 0;  }
    }
    int c = 0;
    for (int i = 0; i < 4; i++) { g_mask4[i] = m[i]; c += m[i]; }
    g_cnt = c;
    g_aux = 0.0;
}

// ---------------- depthwise conv k=3, pad=1 (skips unmasked batches) ----------------
// TH/BB = 1572864 elems per batch = 6144 blocks of 256 -> block maps to one batch
__global__ __launch_bounds__(256) void k_dwconv(
    const float* __restrict__ prev, const float* __restrict__ w,
    const float* __restrict__ bias, float* __restrict__ out)
{
    if (!g_mask4[blockIdx.x / 6144]) return;
    int idx = blockIdx.x * 256 + threadIdx.x;
    int t = idx / HH;
    int h = idx - t * HH;
    int s = t & (SS - 1);
    float acc = bias[h];
    const float* wp = w + h * 3;
    if (s > 0)      acc += prev[idx - HH] * wp[0];
    acc += prev[idx] * wp[1];
    if (s < SS - 1) acc += prev[idx + HH] * wp[2];
    out[idx] = acc;
}

// ---------------- TF32 wmma NT GEMM, 3-stage cp.async pipeline ----------------
// C[8192,768] = A[8192,768] * W[768,768]^T + bias.  act: 0 none, 1 exact GELU.
// 128x128 CTA tile, BK=32, 8 warps (64x32 each), 3 smem stages.
// Blocks belonging to unmasked batches exit immediately (16 row-tiles per batch).
#define GL 36                       // padded row stride (floats)
#define GTILE (128 * GL)            // floats per tile (A or W)
#define GSTG  (2 * GTILE)           // floats per stage (A + W)
#define GS_BYTES (3 * GSTG * 4)     // 110592 B dynamic smem

__device__ __forceinline__ void g6_load(
    const float* __restrict__ A, const float* __restrict__ W,
    uint32_t sb, int bm, int bn, int c, int slot, int tid)
{
    int k0 = c * 32;
    uint32_t abase = sb + (uint32_t)slot * (GSTG * 4);
    uint32_t wbase = abase + GTILE * 4;
    #pragma unroll
    for (int i = 0; i < 4; i++) {
        int idx = tid + i * 256;          // 0..1023
        int r = idx >> 3;                 // row 0..127
        int j = idx & 7;                  // 16B block 0..7
        uint32_t d = (uint32_t)(r * (GL * 4) + j * 16);
        CP16(abase + d, A + (size_t)(bm + r) * HH + k0 + j * 4);
        CP16(wbase + d, W + (size_t)(bn + r) * HH + k0 + j * 4);
    }
}

__global__ __launch_bounds__(256) void gemm_tc(
    const float* __restrict__ A, const float* __restrict__ W,
    const float* __restrict__ bias, float* __restrict__ C, int act)
{
    if (!g_mask4[blockIdx.y >> 4]) return;     // 16 tiles of 128 rows per batch
    extern __shared__ __align__(16) float gsm[];
    uint32_t sb = smem_u32(gsm);
    int tid = threadIdx.x;
    int wid = tid >> 5;
    int lane = tid & 31;
    int wm = wid >> 2;        // 0..1 (64 rows each)
    int wn = wid & 3;         // 0..3 (32 cols each)
    int bm = blockIdx.y * 128, bn = blockIdx.x * 128;

    wmma::fragment<wmma::accumulator, 16, 16, 8, float> acc[4][2];
    #pragma unroll
    for (int i = 0; i < 4; i++)
        #pragma unroll
        for (int j = 0; j < 2; j++) wmma::fill_fragment(acc[i][j], 0.0f);

    // preload stages 0,1
    g6_load(A, W, sb, bm, bn, 0, 0, tid);
    CP_COMMIT();
    g6_load(A, W, sb, bm, bn, 1, 1, tid);
    CP_COMMIT();

    for (int c = 0; c < 24; c++) {
        if (c < 23) asm volatile("cp.async.wait_group 1;" ::: "memory");
        else        asm volatile("cp.async.wait_group 0;" ::: "memory");
        __syncthreads();

        int slot = c % 3;
        const float* As = gsm + slot * GSTG;
        const float* Ws = As + GTILE;

        #pragma unroll
        for (int ks = 0; ks < 32; ks += 8) {
            wmma::fragment<wmma::matrix_a, 16, 16, 8, wmma::precision::tf32, wmma::row_major> af;
            wmma::fragment<wmma::matrix_b, 16, 16, 8, wmma::precision::tf32, wmma::col_major> bf[2];
            #pragma unroll
            for (int ni = 0; ni < 2; ni++)
                wmma::load_matrix_sync(bf[ni], &Ws[(wn * 32 + ni * 16) * GL + ks], GL);
            #pragma unroll
            for (int mi = 0; mi < 4; mi++) {
                wmma::load_matrix_sync(af, &As[(wm * 64 + mi * 16) * GL + ks], GL);
                #pragma unroll
                for (int ni = 0; ni < 2; ni++)
                    wmma::mma_sync(acc[mi][ni], af, bf[ni], acc[mi][ni]);
            }
        }

        if (c + 2 < 24) {
            g6_load(A, W, sb, bm, bn, c + 2, (c + 2) % 3, tid);
            CP_COMMIT();
        }
    }

    // epilogue: reuse dynamic smem for staging
    __syncthreads();
    float* Eb = gsm + wid * 256;
    #pragma unroll
    for (int mi = 0; mi < 4; mi++) {
        #pragma unroll
        for (int ni = 0; ni < 2; ni++) {
            wmma::store_matrix_sync(Eb, acc[mi][ni], 16, wmma::mem_row_major);
            __syncwarp();
            int row0 = bm + wm * 64 + mi * 16;
            int col0 = bn + wn * 32 + ni * 16;
            #pragma unroll
            for (int e = lane; e < 256; e += 32) {
                int r = e >> 4, cc = e & 15;
                float v = Eb[e] + bias[col0 + cc];
                if (act == 1) v = 0.5f * v * (1.0f + erff(v * 0.70710678118654752f));
                C[(size_t)(row0 + r) * HH + col0 + cc] = v;
            }
            __syncwarp();
        }
    }
}

// ---------------- block reduce helper ----------------
__device__ __forceinline__ float blockReduceSum(float v, float* sbuf)
{
    __syncthreads();
    int lane = threadIdx.x & 31, w = threadIdx.x >> 5;
    #pragma unroll
    for (int o = 16; o; o >>= 1) v += __shfl_xor_sync(0xffffffffu, v, o);
    if (lane == 0) sbuf[w] = v;
    __syncthreads();
    if (w == 0) {
        v = (lane < 8) ? sbuf[lane] : 0.f;
        #pragma unroll
        for (int o = 4; o; o >>= 1) v += __shfl_xor_sync(0xffffffffu, v, o);
        if (lane == 0) sbuf[0] = v;
    }
    __syncthreads();
    return sbuf[0];
}

// ---------------- LayerNorm over H=768 (skips unmasked batches) ----------------
__global__ __launch_bounds__(256) void ln_kernel(
    const float* __restrict__ in, const float* __restrict__ g,
    const float* __restrict__ bta, float* __restrict__ outp)
{
    int row = blockIdx.x;
    if (!g_mask4[row >> 11]) return;
    __shared__ float sbuf[8];
    int tid = threadIdx.x;
    const float* rp = in + (size_t)row * HH;
    float v0 = rp[tid], v1 = rp[tid + 256], v2 = rp[tid + 512];
    float sum = blockReduceSum(v0 + v1 + v2, sbuf);
    float mean = sum * (1.0f / 768.0f);
    float d0 = v0 - mean, d1 = v1 - mean, d2 = v2 - mean;
    float sq = blockReduceSum(d0 * d0 + d1 * d1 + d2 * d2, sbuf);
    float scale = rsqrtf(sq * (1.0f / 768.0f) + 1e-5f);
    float* op = outp + (size_t)row * HH;
    op[tid]       = d0 * scale * g[tid]       + bta[tid];
    op[tid + 256] = d1 * scale * g[tid + 256] + bta[tid + 256];
    op[tid + 512] = d2 * scale * g[tid + 512] + bta[tid + 512];
}

// ---------------- flash attention, tf32 wmma, BQ=128, BK=64, HD=64 ----------------
#define ALD 68
__global__ __launch_bounds__(256) void attn_tc(
    const float* __restrict__ Qg, const float* __restrict__ Kg,
    const float* __restrict__ Vg, float* __restrict__ Og)
{
    if (!g_mask4[blockIdx.z]) return;
    extern __shared__ float sm[];
    float* Qs = sm;                       // 128*ALD
    float* Ks = sm + 128 * ALD;           // 64*ALD
    float* Vs = sm + 128 * ALD + 64 * ALD;
    float* Ps = sm + 128 * ALD + 2 * 64 * ALD;   // 128*ALD
    float* Os = Ps;

    int tid = threadIdx.x;
    int wid = tid >> 5;
    int wqm = wid >> 1;
    int wqn = wid & 1;
    int row = tid >> 1;
    int half = tid & 1;
    int qt = blockIdx.x, hh = blockIdx.y, b = blockIdx.z;
    size_t base = (size_t)b * SS * HH + hh * HD;

    #pragma unroll
    for (int u = 0; u < 8; u++) {
        int f4 = tid + u * 256;
        int r = f4 >> 4;
        int c = (f4 & 15) * 4;
        float4 qv = *(const float4*)(Qg + base + (size_t)(qt * 128 + r) * HH + c);
        qv.x *= 0.125f; qv.y *= 0.125f; qv.z *= 0.125f; qv.w *= 0.125f;
        *(float4*)&Qs[r * ALD + c] = tf4(qv);
    }

    const float NEG_INF = __int_as_float(0xff800000u);
    float m_i = NEG_INF, l_i = 0.f;
    float oacc[32];
    #pragma unroll
    for (int j = 0; j < 32; j++) oacc[j] = 0.f;

    for (int kt = 0; kt < SS / 64; kt++) {
        __syncthreads();
        #pragma unroll
        for (int u = 0; u < 4; u++) {
            int f4 = tid + u * 256;
            int r = f4 >> 4;
            int c = (f4 & 15) * 4;
            size_t gofs = base + (size_t)(kt * 64 + r) * HH + c;
            *(float4*)&Ks[r * ALD + c] = tf4(*(const float4*)(Kg + gofs));
            *(float4*)&Vs[r * ALD + c] = tf4(*(const float4*)(Vg + gofs));
        }
        __syncthreads();

        {
            wmma::fragment<wmma::accumulator, 16, 16, 8, float> sc[2][2];
            #pragma unroll
            for (int mi = 0; mi < 2; mi++)
                #pragma unroll
                for (int nj = 0; nj < 2; nj++) wmma::fill_fragment(sc[mi][nj], 0.f);
            #pragma unroll
            for (int ks = 0; ks < 64; ks += 8) {
                wmma::fragment<wmma::matrix_b, 16, 16, 8, wmma::precision::tf32, wmma::col_major> kb[2];
                #pragma unroll
                for (int nj = 0; nj < 2; nj++)
                    wmma::load_matrix_sync(kb[nj], &Ks[(wqn * 32 + nj * 16) * ALD + ks], ALD);
                #pragma unroll
                for (int mi = 0; mi < 2; mi++) {
                    wmma::fragment<wmma::matrix_a, 16, 16, 8, wmma::precision::tf32, wmma::row_major> qa;
                    wmma::load_matrix_sync(qa, &Qs[(wqm * 32 + mi * 16) * ALD + ks], ALD);
                    #pragma unroll
                    for (int nj = 0; nj < 2; nj++)
                        wmma::mma_sync(sc[mi][nj], qa, kb[nj], sc[mi][nj]);
                }
            }
            #pragma unroll
            for (int mi = 0; mi < 2; mi++)
                #pragma unroll
                for (int nj = 0; nj < 2; nj++)
                    wmma::store_matrix_sync(
                        &Ps[(wqm * 32 + mi * 16) * ALD + wqn * 32 + nj * 16],
                        sc[mi][nj], ALD, wmma::mem_row_major);
        }
        __syncthreads();

        {
            float p[32];
            float* pr = &Ps[row * ALD + half * 32];
            #pragma unroll
            for (int u = 0; u < 8; u++) {
                float4 v = *(float4*)&pr[u * 4];
                p[u * 4 + 0] = v.x; p[u * 4 + 1] = v.y;
                p[u * 4 + 2] = v.z; p[u * 4 + 3] = v.w;
            }
            float mx = p[0];
            #pragma unroll
            for (int j = 1; j < 32; j++) mx = fmaxf(mx, p[j]);
            mx = fmaxf(mx, __shfl_xor_sync(0xffffffffu, mx, 1));
            float mn = fmaxf(m_i, mx);
            float corr = __expf(m_i - mn);
            m_i = mn;
            float rs = 0.f;
            #pragma unroll
            for (int j = 0; j < 32; j++) { p[j] = __expf(p[j] - mn); rs += p[j]; }
            rs += __shfl_xor_sync(0xffffffffu, rs, 1);
            l_i = l_i * corr + rs;
            #pragma unroll
            for (int j = 0; j < 32; j++) oacc[j] *= corr;
            #pragma unroll
            for (int u = 0; u < 8; u++) {
                float4 v = make_float4(p[u * 4], p[u * 4 + 1], p[u * 4 + 2], p[u * 4 + 3]);
                *(float4*)&pr[u * 4] = tf4(v);
            }
        }
        __syncthreads();

        wmma::fragment<wmma::accumulator, 16, 16, 8, float> ov[2][2];
        #pragma unroll
        for (int mi = 0; mi < 2; mi++)
            #pragma unroll
            for (int nj = 0; nj < 2; nj++) wmma::fill_fragment(ov[mi][nj], 0.f);
        #pragma unroll
        for (int ks = 0; ks < 64; ks += 8) {
            wmma::fragment<wmma::matrix_b, 16, 16, 8, wmma::precision::tf32, wmma::row_major> vb[2];
            #pragma unroll
            for (int nj = 0; nj < 2; nj++)
                wmma::load_matrix_sync(vb[nj], &Vs[ks * ALD + wqn * 32 + nj * 16], ALD);
            #pragma unroll
            for (int mi = 0; mi < 2; mi++) {
                wmma::fragment<wmma::matrix_a, 16, 16, 8, wmma::precision::tf32, wmma::row_major> pa;
                wmma::load_matrix_sync(pa, &Ps[(wqm * 32 + mi * 16) * ALD + ks], ALD);
                #pragma unroll
                for (int nj = 0; nj < 2; nj++)
                    wmma::mma_sync(ov[mi][nj], pa, vb[nj], ov[mi][nj]);
            }
        }
        __syncthreads();
        #pragma unroll
        for (int mi = 0; mi < 2; mi++)
            #pragma unroll
            for (int nj = 0; nj < 2; nj++)
                wmma::store_matrix_sync(
                    &Os[(wqm * 32 + mi * 16) * ALD + wqn * 32 + nj * 16],
                    ov[mi][nj], ALD, wmma::mem_row_major);
        __syncthreads();

        {
            float* orow = &Os[row * ALD + half * 32];
            #pragma unroll
            for (int u = 0; u < 8; u++) {
                float4 v = *(float4*)&orow[u * 4];
                oacc[u * 4 + 0] += v.x; oacc[u * 4 + 1] += v.y;
                oacc[u * 4 + 2] += v.z; oacc[u * 4 + 3] += v.w;
            }
        }
    }

    float inv = 1.0f / l_i;
    float* op = Og + base + (size_t)(qt * 128 + row) * HH + half * 32;
    #pragma unroll
    for (int u = 0; u < 8; u++) {
        float4 v = make_float4(oacc[u * 4] * inv, oacc[u * 4 + 1] * inv,
                               oacc[u * 4 + 2] * inv, oacc[u * 4 + 3] * inv);
        *(float4*)&op[u * 4] = v;
    }
}

// ---------------- fused gate + final: one block per token ----------------
// masked:   gate = sigmoid([x,br].Wg + bg); out = x + gate*tanh(inj); aux += (br-x)^2
// unmasked: out = x (exact copy)
__global__ __launch_bounds__(256) void final_fused(
    const float* __restrict__ x, const float* __restrict__ br,
    const float* __restrict__ inj, const float* __restrict__ Wg,
    const float* __restrict__ bg, float* __restrict__ outp)
{
    int t = blockIdx.x;
    int tid = threadIdx.x;
    const float* xr = x + (size_t)t * HH;
    float* orow = outp + (size_t)t * HH;

    if (!g_mask4[t >> 11]) {
        if (tid < 192)
            ((float4*)orow)[tid] = ((const float4*)xr)[tid];
        return;
    }

    __shared__ float sbuf[8];
    const float* brr = br + (size_t)t * HH;
    const float* ir  = inj + (size_t)t * HH;

    float xv0 = xr[tid],        xv1 = xr[tid + 256],        xv2 = xr[tid + 512];
    float bv0 = brr[tid],       bv1 = brr[tid + 256],       bv2 = brr[tid + 512];

    float z = xv0 * Wg[tid] + xv1 * Wg[tid + 256] + xv2 * Wg[tid + 512]
            + bv0 * Wg[HH + tid] + bv1 * Wg[HH + tid + 256] + bv2 * Wg[HH + tid + 512];
    z = blockReduceSum(z, sbuf);
    float gate = 1.0f / (1.0f + __expf(-(z + bg[0])));

    orow[tid]       = xv0 + gate * tanhf(ir[tid]);
    orow[tid + 256] = xv1 + gate * tanhf(ir[tid + 256]);
    orow[tid + 512] = xv2 + gate * tanhf(ir[tid + 512]);

    float d0 = bv0 - xv0, d1 = bv1 - xv1, d2 = bv2 - xv2;
    float a = blockReduceSum(d0 * d0 + d1 * d1 + d2 * d2, sbuf);
    if (tid == 0) atomicAdd(&g_aux, (double)a);
}

__global__ void auxfin_kernel(float* outp, int out_size)
{
    if (out_size > TH) {
        int c = g_cnt; if (c < 1) c = 1;
        outp[TH] = (float)(g_aux / ((double)c * (double)SS * (double)HH));
    }
}

// ---------------- launch ----------------
extern "C" void kernel_launch(void* const* d_in, const int* in_sizes, int n_in,
                              void* d_out, int out_size)
{
    const float* x      = (const float*)d_in[0];
    const float* prev   = (const float*)d_in[1];
    const void*  maskp  = d_in[2];
    const float* dww    = (const float*)d_in[3];
    const float* dwb    = (const float*)d_in[4];
    const float* pww    = (const float*)d_in[5];
    const float* pwb    = (const float*)d_in[6];
    const float* cng    = (const float*)d_in[7];
    const float* cnb    = (const float*)d_in[8];
    const float* Wq     = (const float*)d_in[9];
    const float* bq     = (const float*)d_in[10];
    const float* Wk     = (const float*)d_in[11];
    const float* bk     = (const float*)d_in[12];
    const float* Wv     = (const float*)d_in[13];
    const float* bv     = (const float*)d_in[14];
    const float* Wo     = (const float*)d_in[15];
    const float* bo     = (const float*)d_in[16];
    const float* png    = (const float*)d_in[17];
    const float* pnb    = (const float*)d_in[18];
    const float* Wpost  = (const float*)d_in[19];
    const float* bpost  = (const float*)d_in[20];
    const float* Wg     = (const float*)d_in[21];
    const float* bg     = (const float*)d_in[22];
    float* out = (float*)d_out;

    float *p_dw, *p_t0, *p_t1, *p_t2, *p_br, *p_q, *p_k, *p_v;
    cudaGetSymbolAddress((void**)&p_dw, g_dw);
    cudaGetSymbolAddress((void**)&p_t0, g_t0);
    cudaGetSymbolAddress((void**)&p_t1, g_t1);
    cudaGetSymbolAddress((void**)&p_t2, g_t2);
    cudaGetSymbolAddress((void**)&p_br, g_br);
    cudaGetSymbolAddress((void**)&p_q,  g_q);
    cudaGetSymbolAddress((void**)&p_k,  g_k);
    cudaGetSymbolAddress((void**)&p_v,  g_v);

    const int ATTN_SMEM = (128 * ALD + 64 * ALD * 2 + 128 * ALD) * 4;   // 104448 B
    cudaFuncSetAttribute(attn_tc, cudaFuncAttributeMaxDynamicSharedMemorySize, ATTN_SMEM);
    cudaFuncSetAttribute(gemm_tc, cudaFuncAttributeMaxDynamicSharedMemorySize, GS_BYTES);

    dim3 ggrid(HH / 128, TT / 128);  // (6, 64)

    k_setup<<<1, 1>>>(maskp);
    k_dwconv<<<TH / 256, 256>>>(prev, dww, dwb, p_dw);
    gemm_tc<<<ggrid, 256, GS_BYTES>>>(p_dw, pww, pwb, p_t0, 1);     // PW + GELU
    ln_kernel<<<TT, 256>>>(p_t0, cng, cnb, p_br);                   // bridged
    gemm_tc<<<ggrid, 256, GS_BYTES>>>(x,    Wq, bq, p_q, 0);
    gemm_tc<<<ggrid, 256, GS_BYTES>>>(p_br, Wk, bk, p_k, 0);
    gemm_tc<<<ggrid, 256, GS_BYTES>>>(p_br, Wv, bv, p_v, 0);
    attn_tc<<<dim3(SS / 128, NH, BB), 256, ATTN_SMEM>>>(p_q, p_k, p_v, p_t0);
    gemm_tc<<<ggrid, 256, GS_BYTES>>>(p_t0, Wo, bo, p_t1, 0);
    ln_kernel<<<TT, 256>>>(p_t1, png, pnb, p_t2);
    gemm_tc<<<ggrid, 256, GS_BYTES>>>(p_t2, Wpost, bpost, p_t1, 0); // inj
    final_fused<<<TT, 256>>>(x, p_br, p_t1, Wg, bg, out);
    auxfin_kernel<<<1, 1>>>(out, out_size);
}